// round 5
// baseline (speedup 1.0000x reference)
#include <cuda_runtime.h>

#define BATCH 64
#define SEQ   64
#define EMBED 1024
#define NHEAD 16
#define HDIM  64
#define VOCAB 50257
#define M_TOT (BATCH*SEQ)   /* 4096 */

typedef unsigned long long u64;

// ---------------- scratch (no allocation allowed) ----------------
__device__ float g_emb[M_TOT*EMBED];
__device__ float g_q  [M_TOT*EMBED];
__device__ float g_k  [M_TOT*EMBED];
__device__ float g_v  [M_TOT*EMBED];
__device__ float g_cat[M_TOT*EMBED];
__device__ float g_y  [M_TOT*EMBED];

// ---------------- f32x2 helpers (Blackwell packed fp32) ----------------
__device__ __forceinline__ u64 pack2(float x, float y) {
    u64 r;
    asm("mov.b64 %0, {%1, %2};" : "=l"(r) : "f"(x), "f"(y));
    return r;
}
__device__ __forceinline__ void unpack2(u64 v, float& x, float& y) {
    asm("mov.b64 {%0, %1}, %2;" : "=f"(x), "=f"(y) : "l"(v));
}
__device__ __forceinline__ void fma2(u64& d, u64 a, u64 b) {
    asm("fma.rn.f32x2 %0, %1, %2, %0;" : "+l"(d) : "l"(a), "l"(b));
}

// ---------------- embed: emb[b,s,:] = E[x[b,s],:] + pe[s,:] ----------------
__global__ void __launch_bounds__(256) embed_kernel(const int* __restrict__ x,
                                                    const float* __restrict__ E,
                                                    const float* __restrict__ pe)
{
    int idx = blockIdx.x * 256 + threadIdx.x;     // float4 index, 0 .. 4096*256-1
    int row = idx >> 8;                            // 0..4095
    int c   = (idx & 255) << 2;                    // 0..1020
    int tok = x[row];
    float4 e = *(const float4*)(E  + (size_t)tok * EMBED + c);
    float4 p = *(const float4*)(pe + (size_t)(row & 63) * EMBED + c);
    e.x += p.x; e.y += p.y; e.z += p.z; e.w += p.w;
    *(float4*)(g_emb + (size_t)row * EMBED + c) = e;
}

// ---------------- shared 128x128x16 inner product on FFMA2 ----------------
__device__ __forceinline__ void mm_tile(const float (&sA)[16][128],
                                        const float (&sB)[16][128],
                                        u64 (&acc)[8][4], int tx, int ty)
{
    #pragma unroll
    for (int kk = 0; kk < 16; kk++) {
        float4 a0 = *(const float4*)(&sA[kk][ty * 8]);
        float4 a1 = *(const float4*)(&sA[kk][ty * 8 + 4]);
        float4 b0 = *(const float4*)(&sB[kk][tx * 8]);
        float4 b1 = *(const float4*)(&sB[kk][tx * 8 + 4]);
        u64 bb0 = pack2(b0.x, b0.y), bb1 = pack2(b0.z, b0.w);
        u64 bb2 = pack2(b1.x, b1.y), bb3 = pack2(b1.z, b1.w);
        float a[8] = {a0.x, a0.y, a0.z, a0.w, a1.x, a1.y, a1.z, a1.w};
        #pragma unroll
        for (int i = 0; i < 8; i++) {
            u64 ai = pack2(a[i], a[i]);
            fma2(acc[i][0], ai, bb0);
            fma2(acc[i][1], ai, bb1);
            fma2(acc[i][2], ai, bb2);
            fma2(acc[i][3], ai, bb3);
        }
    }
}

// ---------------- QKV projection: out[b,h,s,e] = emb @ Wq[h] + bq[h] ----------------
// W layout: [H][D][hd]; logical B(d, n) = W[(n>>6)*D*hd + d*hd + (n&63)], n = h*64+e
__global__ void __launch_bounds__(256) qkv_gemm(const float* __restrict__ W,
                                                const float* __restrict__ bias,
                                                int which)
{
    __shared__ float sA[16][128];
    __shared__ float sB[16][128];
    float* out = (which == 0) ? g_q : (which == 1) ? g_k : g_v;
    int tid = threadIdx.x;
    int tx = tid & 15, ty = tid >> 4;
    int m0 = blockIdx.x * 128;
    int n0 = blockIdx.y * 128;
    u64 acc[8][4] = {};
    for (int k0 = 0; k0 < EMBED; k0 += 16) {
        #pragma unroll
        for (int i = 0; i < 2; i++) {
            int idx = tid + i * 256;
            int r = idx >> 2, c = (idx & 3) << 2;
            float4 v = *(const float4*)(g_emb + (size_t)(m0 + r) * EMBED + k0 + c);
            sA[c + 0][r] = v.x; sA[c + 1][r] = v.y; sA[c + 2][r] = v.z; sA[c + 3][r] = v.w;
        }
        #pragma unroll
        for (int i = 0; i < 2; i++) {
            int idx = tid + i * 256;
            int br = idx >> 5, bc = (idx & 31) << 2;
            int n = n0 + bc;
            float4 v = *(const float4*)(W + (size_t)(n >> 6) * (EMBED * HDIM)
                                          + (size_t)(k0 + br) * HDIM + (n & 63));
            *(float4*)(&sB[br][bc]) = v;
        }
        __syncthreads();
        mm_tile(sA, sB, acc, tx, ty);
        __syncthreads();
    }
    #pragma unroll
    for (int i = 0; i < 8; i++) {
        int m = m0 + ty * 8 + i;
        int b = m >> 6, s = m & 63;
        #pragma unroll
        for (int j = 0; j < 4; j++) {
            float x0, x1;
            unpack2(acc[i][j], x0, x1);
            int n = n0 + tx * 8 + j * 2;
            int h = n >> 6, e = n & 63;
            float* dst = out + (size_t)(((b * NHEAD + h) * SEQ + s) * HDIM + e);
            dst[0] = x0 + bias[n];
            dst[1] = x1 + bias[n + 1];
        }
    }
}

// ---------------- attention: one block per (b,h) ----------------
__global__ void __launch_bounds__(256) attn_kernel()
{
    __shared__ float sQ [64][68];   // pad 68: conflict-free + 16B aligned rows
    __shared__ float sKV[64][68];
    int bh  = blockIdx.x;
    int tid = threadIdx.x;
    const float* qb = g_q + (size_t)bh * (SEQ * HDIM);
    const float* kb = g_k + (size_t)bh * (SEQ * HDIM);
    const float* vb = g_v + (size_t)bh * (SEQ * HDIM);
    #pragma unroll
    for (int i = 0; i < 4; i++) {
        int idx = tid + i * 256;
        int r = idx >> 4, c = (idx & 15) << 2;
        *(float4*)(&sQ [r][c]) = *(const float4*)(qb + r * 64 + c);
        *(float4*)(&sKV[r][c]) = *(const float4*)(kb + r * 64 + c);
    }
    __syncthreads();

    int s = tid >> 2, q = tid & 3;   // thread handles row s, columns t = q + 4j
    float4 qv[16];
    #pragma unroll
    for (int k4 = 0; k4 < 16; k4++) qv[k4] = *(const float4*)(&sQ[s][k4 * 4]);

    float sc[16];
    #pragma unroll
    for (int j = 0; j < 16; j++) {
        int t = q + 4 * j;
        float d = 0.f;
        #pragma unroll
        for (int k4 = 0; k4 < 16; k4++) {
            float4 kv = *(const float4*)(&sKV[t][k4 * 4]);
            d += qv[k4].x * kv.x + qv[k4].y * kv.y + qv[k4].z * kv.z + qv[k4].w * kv.w;
        }
        sc[j] = (t <= s) ? d * 0.125f : -1e30f;   // causal mask + 1/sqrt(64)
    }
    // softmax across the 4-lane group that shares row s
    float mx = sc[0];
    #pragma unroll
    for (int j = 1; j < 16; j++) mx = fmaxf(mx, sc[j]);
    mx = fmaxf(mx, __shfl_xor_sync(0xFFFFFFFFu, mx, 1));
    mx = fmaxf(mx, __shfl_xor_sync(0xFFFFFFFFu, mx, 2));
    float sum = 0.f;
    #pragma unroll
    for (int j = 0; j < 16; j++) { sc[j] = __expf(sc[j] - mx); sum += sc[j]; }
    sum += __shfl_xor_sync(0xFFFFFFFFu, sum, 1);
    sum += __shfl_xor_sync(0xFFFFFFFFu, sum, 2);
    float inv = 1.f / sum;
    #pragma unroll
    for (int j = 0; j < 16; j++) sc[j] *= inv;

    __syncthreads();   // done with K
    #pragma unroll
    for (int i = 0; i < 4; i++) {
        int idx = tid + i * 256;
        int r = idx >> 4, c = (idx & 15) << 2;
        *(float4*)(&sKV[r][c]) = *(const float4*)(vb + r * 64 + c);
    }
    __syncthreads();

    float po[64];
    #pragma unroll
    for (int e = 0; e < 64; e++) po[e] = 0.f;
    #pragma unroll
    for (int j = 0; j < 16; j++) {
        int t = q + 4 * j;
        float w = sc[j];
        #pragma unroll
        for (int e4 = 0; e4 < 16; e4++) {
            float4 v = *(const float4*)(&sKV[t][e4 * 4]);
            po[e4 * 4 + 0] += w * v.x;
            po[e4 * 4 + 1] += w * v.y;
            po[e4 * 4 + 2] += w * v.z;
            po[e4 * 4 + 3] += w * v.w;
        }
    }
    #pragma unroll
    for (int e = 0; e < 64; e++) {
        po[e] += __shfl_xor_sync(0xFFFFFFFFu, po[e], 1);
        po[e] += __shfl_xor_sync(0xFFFFFFFFu, po[e], 2);
    }
    // write to cat layout [B,S,H*hd]; this thread owns e in [16q, 16q+16)
    int b = bh >> 4, h = bh & 15;
    float* dst = g_cat + (size_t)b * (SEQ * EMBED) + (size_t)s * EMBED + h * HDIM + q * 16;
    #pragma unroll
    for (int i = 0; i < 4; i++) {
        int e0 = q * 16 + i * 4;
        *(float4*)(dst + i * 4) = make_float4(po[e0], po[e0 + 1], po[e0 + 2], po[e0 + 3]);
    }
}

// ---------------- output projection + residual: y = cat @ Wo + bo + emb ----------------
__global__ void __launch_bounds__(256) wo_gemm(const float* __restrict__ Wo,
                                               const float* __restrict__ bo)
{
    __shared__ float sA[16][128];
    __shared__ float sB[16][128];
    int tid = threadIdx.x;
    int tx = tid & 15, ty = tid >> 4;
    int m0 = blockIdx.x * 128;
    int n0 = blockIdx.y * 128;
    u64 acc[8][4] = {};
    for (int k0 = 0; k0 < EMBED; k0 += 16) {
        #pragma unroll
        for (int i = 0; i < 2; i++) {
            int idx = tid + i * 256;
            int r = idx >> 2, c = (idx & 3) << 2;
            float4 v = *(const float4*)(g_cat + (size_t)(m0 + r) * EMBED + k0 + c);
            sA[c + 0][r] = v.x; sA[c + 1][r] = v.y; sA[c + 2][r] = v.z; sA[c + 3][r] = v.w;
        }
        #pragma unroll
        for (int i = 0; i < 2; i++) {
            int idx = tid + i * 256;
            int br = idx >> 5, bc = (idx & 31) << 2;
            *(float4*)(&sB[br][bc]) =
                *(const float4*)(Wo + (size_t)(k0 + br) * EMBED + n0 + bc);
        }
        __syncthreads();
        mm_tile(sA, sB, acc, tx, ty);
        __syncthreads();
    }
    #pragma unroll
    for (int i = 0; i < 8; i++) {
        int m = m0 + ty * 8 + i;
        size_t rowoff = (size_t)m * EMBED;
        #pragma unroll
        for (int j = 0; j < 4; j++) {
            float x0, x1;
            unpack2(acc[i][j], x0, x1);
            int n = n0 + tx * 8 + j * 2;
            g_y[rowoff + n]     = x0 + bo[n]     + g_emb[rowoff + n];
            g_y[rowoff + n + 1] = x1 + bo[n + 1] + g_emb[rowoff + n + 1];
        }
    }
}

// ---------------- logits: out = y @ Wu + bu  (the 421-GFLOP kernel) ----------------
// NOTE: Wu rows have stride 50257 floats (odd) -> rows are only 4-byte aligned.
// All Wu traffic must use scalar 32-bit loads; float4 loads trap (misaligned).
__global__ void __launch_bounds__(256) wu_gemm(const float* __restrict__ Wu,
                                               const float* __restrict__ bu,
                                               float* __restrict__ out)
{
    __shared__ float sA[16][128];
    __shared__ float sB[16][128];
    int tid = threadIdx.x;
    int tx = tid & 15, ty = tid >> 4;
    int m0 = blockIdx.x * 128;
    int n0 = blockIdx.y * 128;
    u64 acc[8][4] = {};
    for (int k0 = 0; k0 < EMBED; k0 += 16) {
        #pragma unroll
        for (int i = 0; i < 2; i++) {
            int idx = tid + i * 256;
            int r = idx >> 2, c = (idx & 3) << 2;
            float4 v = *(const float4*)(g_y + (size_t)(m0 + r) * EMBED + k0 + c);
            sA[c + 0][r] = v.x; sA[c + 1][r] = v.y; sA[c + 2][r] = v.z; sA[c + 3][r] = v.w;
        }
        // B tile: scalar loads only (odd row stride => 4B alignment)
        #pragma unroll
        for (int i = 0; i < 2; i++) {
            int idx = tid + i * 256;
            int br = idx >> 5, bc = (idx & 31) << 2;
            const float* src = Wu + (size_t)(k0 + br) * VOCAB;
            #pragma unroll
            for (int jj = 0; jj < 4; jj++) {
                int n = n0 + bc + jj;
                sB[br][bc + jj] = (n < VOCAB) ? __ldg(src + n) : 0.f;
            }
        }
        __syncthreads();
        mm_tile(sA, sB, acc, tx, ty);
        __syncthreads();
    }
    #pragma unroll
    for (int i = 0; i < 8; i++) {
        int m = m0 + ty * 8 + i;
        size_t rowoff = (size_t)m * VOCAB;
        #pragma unroll
        for (int j = 0; j < 4; j++) {
            float x0, x1;
            unpack2(acc[i][j], x0, x1);
            int n = n0 + tx * 8 + j * 2;
            if (n < VOCAB)     out[rowoff + n]     = x0 + bu[n];
            if (n + 1 < VOCAB) out[rowoff + n + 1] = x1 + bu[n + 1];
        }
    }
}

// ---------------- launch ----------------
extern "C" void kernel_launch(void* const* d_in, const int* in_sizes, int n_in,
                              void* d_out, int out_size)
{
    const int*   x  = (const int*)  d_in[0];
    const float* E  = (const float*)d_in[1];
    const float* pe = (const float*)d_in[2];
    const float* Wq = (const float*)d_in[3];
    const float* bq = (const float*)d_in[4];
    const float* Wk = (const float*)d_in[5];
    const float* bk = (const float*)d_in[6];
    const float* Wv = (const float*)d_in[7];
    const float* bv = (const float*)d_in[8];
    const float* Wo = (const float*)d_in[9];
    const float* bo = (const float*)d_in[10];
    const float* Wu = (const float*)d_in[11];
    const float* bu = (const float*)d_in[12];
    float* out = (float*)d_out;

    embed_kernel<<<4096, 256>>>(x, E, pe);

    dim3 gq(M_TOT / 128, EMBED / 128);            // (32, 8)
    qkv_gemm<<<gq, 256>>>(Wq, bq, 0);
    qkv_gemm<<<gq, 256>>>(Wk, bk, 1);
    qkv_gemm<<<gq, 256>>>(Wv, bv, 2);

    attn_kernel<<<BATCH * NHEAD, 256>>>();

    wo_gemm<<<dim3(M_TOT / 128, EMBED / 128), 256>>>(Wo, bo);

    dim3 gu(M_TOT / 128, (VOCAB + 127) / 128);    // (32, 393)
    wu_gemm<<<gu, 256>>>(Wu, bu, out);
}

// round 8
// speedup vs baseline: 2.5599x; 2.5599x over previous
#include <cuda_runtime.h>
#include <cuda_bf16.h>
#include <cstdint>

#define BATCH 64
#define SEQ   64
#define EMBED 1024
#define NHEAD 16
#define HDIM  64
#define VOCAB 50257
#define M_TOT (BATCH*SEQ)   /* 4096 */

#define N_PAD  50304        /* 393*128 */
#define K_EFF  3072         /* 3 x 1024 split sections */
#define WU_NK  (K_EFF/32)   /* 96 k-steps */

typedef unsigned long long u64;

// ---------------- scratch (no allocation allowed) ----------------
__device__ float g_emb[M_TOT*EMBED];
__device__ float g_q  [M_TOT*EMBED];
__device__ float g_k  [M_TOT*EMBED];
__device__ float g_v  [M_TOT*EMBED];
__device__ float g_cat[M_TOT*EMBED];
__device__ float g_y  [M_TOT*EMBED];
// split-bf16 operands for the logits GEMM
__device__ __align__(16) __nv_bfloat16 g_A2[(size_t)M_TOT * K_EFF];   // [4096][3072]  A = [hi|lo|hi]
__device__ __align__(16) __nv_bfloat16 g_B2[(size_t)N_PAD * K_EFF];   // [50304][3072] B = [hi|hi|lo] (K-major)

// ---------------- f32x2 helpers (Blackwell packed fp32) ----------------
__device__ __forceinline__ u64 pack2(float x, float y) {
    u64 r; asm("mov.b64 %0, {%1, %2};" : "=l"(r) : "f"(x), "f"(y)); return r;
}
__device__ __forceinline__ void unpack2(u64 v, float& x, float& y) {
    asm("mov.b64 {%0, %1}, %2;" : "=f"(x), "=f"(y) : "l"(v));
}
__device__ __forceinline__ void fma2(u64& d, u64 a, u64 b) {
    asm("fma.rn.f32x2 %0, %1, %2, %0;" : "+l"(d) : "l"(a), "l"(b));
}

// ---------------- mma.sync / ldmatrix / cp.async helpers (sm_80+ generic) ----------------
__device__ __forceinline__ uint32_t smem_u32(const void* p) {
    uint32_t a;
    asm("{ .reg .u64 t; cvta.to.shared.u64 t, %1; cvt.u32.u64 %0, t; }" : "=r"(a) : "l"(p));
    return a;
}
__device__ __forceinline__ void cp16(uint32_t dst, const void* src) {
    asm volatile("cp.async.cg.shared.global [%0], [%1], 16;" :: "r"(dst), "l"(src) : "memory");
}
#define CP_COMMIT() asm volatile("cp.async.commit_group;" ::: "memory")
#define CP_WAIT(N)  asm volatile("cp.async.wait_group %0;" :: "n"(N) : "memory")

__device__ __forceinline__ void ldm_x4(uint32_t (&r)[4], uint32_t addr) {
    asm volatile("ldmatrix.sync.aligned.m8n8.x4.shared.b16 {%0,%1,%2,%3}, [%4];"
        : "=r"(r[0]), "=r"(r[1]), "=r"(r[2]), "=r"(r[3]) : "r"(addr));
}
__device__ __forceinline__ void mma_bf16(float (&d)[4], const uint32_t (&a)[4],
                                         uint32_t b0, uint32_t b1) {
    asm volatile("mma.sync.aligned.m16n8k16.row.col.f32.bf16.bf16.f32 "
        "{%0,%1,%2,%3}, {%4,%5,%6,%7}, {%8,%9}, {%0,%1,%2,%3};"
        : "+f"(d[0]), "+f"(d[1]), "+f"(d[2]), "+f"(d[3])
        : "r"(a[0]), "r"(a[1]), "r"(a[2]), "r"(a[3]), "r"(b0), "r"(b1));
}

// ---------------- embed ----------------
__global__ void __launch_bounds__(256) embed_kernel(const int* __restrict__ x,
                                                    const float* __restrict__ E,
                                                    const float* __restrict__ pe)
{
    int idx = blockIdx.x * 256 + threadIdx.x;
    int row = idx >> 8;
    int c   = (idx & 255) << 2;
    int tok = x[row];
    float4 e = *(const float4*)(E  + (size_t)tok * EMBED + c);
    float4 p = *(const float4*)(pe + (size_t)(row & 63) * EMBED + c);
    e.x += p.x; e.y += p.y; e.z += p.z; e.w += p.w;
    *(float4*)(g_emb + (size_t)row * EMBED + c) = e;
}

// ---------------- FFMA2 128x128x16 inner product ----------------
__device__ __forceinline__ void mm_tile(const float (&sA)[16][128],
                                        const float (&sB)[16][128],
                                        u64 (&acc)[8][4], int tx, int ty)
{
    #pragma unroll
    for (int kk = 0; kk < 16; kk++) {
        float4 a0 = *(const float4*)(&sA[kk][ty * 8]);
        float4 a1 = *(const float4*)(&sA[kk][ty * 8 + 4]);
        float4 b0 = *(const float4*)(&sB[kk][tx * 8]);
        float4 b1 = *(const float4*)(&sB[kk][tx * 8 + 4]);
        u64 bb0 = pack2(b0.x, b0.y), bb1 = pack2(b0.z, b0.w);
        u64 bb2 = pack2(b1.x, b1.y), bb3 = pack2(b1.z, b1.w);
        float a[8] = {a0.x, a0.y, a0.z, a0.w, a1.x, a1.y, a1.z, a1.w};
        #pragma unroll
        for (int i = 0; i < 8; i++) {
            u64 ai = pack2(a[i], a[i]);
            fma2(acc[i][0], ai, bb0);
            fma2(acc[i][1], ai, bb1);
            fma2(acc[i][2], ai, bb2);
            fma2(acc[i][3], ai, bb3);
        }
    }
}

// ---------------- QKV projection ----------------
__global__ void __launch_bounds__(256) qkv_gemm(const float* __restrict__ W,
                                                const float* __restrict__ bias,
                                                int which)
{
    __shared__ float sA[16][128];
    __shared__ float sB[16][128];
    float* out = (which == 0) ? g_q : (which == 1) ? g_k : g_v;
    int tid = threadIdx.x;
    int tx = tid & 15, ty = tid >> 4;
    int m0 = blockIdx.x * 128;
    int n0 = blockIdx.y * 128;
    u64 acc[8][4] = {};
    for (int k0 = 0; k0 < EMBED; k0 += 16) {
        #pragma unroll
        for (int i = 0; i < 2; i++) {
            int idx = tid + i * 256;
            int r = idx >> 2, c = (idx & 3) << 2;
            float4 v = *(const float4*)(g_emb + (size_t)(m0 + r) * EMBED + k0 + c);
            sA[c + 0][r] = v.x; sA[c + 1][r] = v.y; sA[c + 2][r] = v.z; sA[c + 3][r] = v.w;
        }
        #pragma unroll
        for (int i = 0; i < 2; i++) {
            int idx = tid + i * 256;
            int br = idx >> 5, bc = (idx & 31) << 2;
            int n = n0 + bc;
            float4 v = *(const float4*)(W + (size_t)(n >> 6) * (EMBED * HDIM)
                                          + (size_t)(k0 + br) * HDIM + (n & 63));
            *(float4*)(&sB[br][bc]) = v;
        }
        __syncthreads();
        mm_tile(sA, sB, acc, tx, ty);
        __syncthreads();
    }
    #pragma unroll
    for (int i = 0; i < 8; i++) {
        int m = m0 + ty * 8 + i;
        int b = m >> 6, s = m & 63;
        #pragma unroll
        for (int j = 0; j < 4; j++) {
            float x0, x1;
            unpack2(acc[i][j], x0, x1);
            int n = n0 + tx * 8 + j * 2;
            int h = n >> 6, e = n & 63;
            float* dst = out + (size_t)(((b * NHEAD + h) * SEQ + s) * HDIM + e);
            dst[0] = x0 + bias[n];
            dst[1] = x1 + bias[n + 1];
        }
    }
}

// ---------------- attention ----------------
__global__ void __launch_bounds__(256) attn_kernel()
{
    __shared__ float sQ [64][68];
    __shared__ float sKV[64][68];
    int bh  = blockIdx.x;
    int tid = threadIdx.x;
    const float* qb = g_q + (size_t)bh * (SEQ * HDIM);
    const float* kb = g_k + (size_t)bh * (SEQ * HDIM);
    const float* vb = g_v + (size_t)bh * (SEQ * HDIM);
    #pragma unroll
    for (int i = 0; i < 4; i++) {
        int idx = tid + i * 256;
        int r = idx >> 4, c = (idx & 15) << 2;
        *(float4*)(&sQ [r][c]) = *(const float4*)(qb + r * 64 + c);
        *(float4*)(&sKV[r][c]) = *(const float4*)(kb + r * 64 + c);
    }
    __syncthreads();

    int s = tid >> 2, q = tid & 3;
    float4 qv[16];
    #pragma unroll
    for (int k4 = 0; k4 < 16; k4++) qv[k4] = *(const float4*)(&sQ[s][k4 * 4]);

    float sc[16];
    #pragma unroll
    for (int j = 0; j < 16; j++) {
        int t = q + 4 * j;
        float d = 0.f;
        #pragma unroll
        for (int k4 = 0; k4 < 16; k4++) {
            float4 kv = *(const float4*)(&sKV[t][k4 * 4]);
            d += qv[k4].x * kv.x + qv[k4].y * kv.y + qv[k4].z * kv.z + qv[k4].w * kv.w;
        }
        sc[j] = (t <= s) ? d * 0.125f : -1e30f;
    }
    float mx = sc[0];
    #pragma unroll
    for (int j = 1; j < 16; j++) mx = fmaxf(mx, sc[j]);
    mx = fmaxf(mx, __shfl_xor_sync(0xFFFFFFFFu, mx, 1));
    mx = fmaxf(mx, __shfl_xor_sync(0xFFFFFFFFu, mx, 2));
    float sum = 0.f;
    #pragma unroll
    for (int j = 0; j < 16; j++) { sc[j] = __expf(sc[j] - mx); sum += sc[j]; }
    sum += __shfl_xor_sync(0xFFFFFFFFu, sum, 1);
    sum += __shfl_xor_sync(0xFFFFFFFFu, sum, 2);
    float inv = 1.f / sum;
    #pragma unroll
    for (int j = 0; j < 16; j++) sc[j] *= inv;

    __syncthreads();
    #pragma unroll
    for (int i = 0; i < 4; i++) {
        int idx = tid + i * 256;
        int r = idx >> 4, c = (idx & 15) << 2;
        *(float4*)(&sKV[r][c]) = *(const float4*)(vb + r * 64 + c);
    }
    __syncthreads();

    float po[64];
    #pragma unroll
    for (int e = 0; e < 64; e++) po[e] = 0.f;
    #pragma unroll
    for (int j = 0; j < 16; j++) {
        int t = q + 4 * j;
        float w = sc[j];
        #pragma unroll
        for (int e4 = 0; e4 < 16; e4++) {
            float4 v = *(const float4*)(&sKV[t][e4 * 4]);
            po[e4 * 4 + 0] += w * v.x;
            po[e4 * 4 + 1] += w * v.y;
            po[e4 * 4 + 2] += w * v.z;
            po[e4 * 4 + 3] += w * v.w;
        }
    }
    #pragma unroll
    for (int e = 0; e < 64; e++) {
        po[e] += __shfl_xor_sync(0xFFFFFFFFu, po[e], 1);
        po[e] += __shfl_xor_sync(0xFFFFFFFFu, po[e], 2);
    }
    int b = bh >> 4, h = bh & 15;
    float* dst = g_cat + (size_t)b * (SEQ * EMBED) + (size_t)s * EMBED + h * HDIM + q * 16;
    #pragma unroll
    for (int i = 0; i < 4; i++) {
        int e0 = q * 16 + i * 4;
        *(float4*)(dst + i * 4) = make_float4(po[e0], po[e0 + 1], po[e0 + 2], po[e0 + 3]);
    }
}

// ---------------- output projection + residual ----------------
__global__ void __launch_bounds__(256) wo_gemm(const float* __restrict__ Wo,
                                               const float* __restrict__ bo)
{
    __shared__ float sA[16][128];
    __shared__ float sB[16][128];
    int tid = threadIdx.x;
    int tx = tid & 15, ty = tid >> 4;
    int m0 = blockIdx.x * 128;
    int n0 = blockIdx.y * 128;
    u64 acc[8][4] = {};
    for (int k0 = 0; k0 < EMBED; k0 += 16) {
        #pragma unroll
        for (int i = 0; i < 2; i++) {
            int idx = tid + i * 256;
            int r = idx >> 2, c = (idx & 3) << 2;
            float4 v = *(const float4*)(g_cat + (size_t)(m0 + r) * EMBED + k0 + c);
            sA[c + 0][r] = v.x; sA[c + 1][r] = v.y; sA[c + 2][r] = v.z; sA[c + 3][r] = v.w;
        }
        #pragma unroll
        for (int i = 0; i < 2; i++) {
            int idx = tid + i * 256;
            int br = idx >> 5, bc = (idx & 31) << 2;
            *(float4*)(&sB[br][bc]) =
                *(const float4*)(Wo + (size_t)(k0 + br) * EMBED + n0 + bc);
        }
        __syncthreads();
        mm_tile(sA, sB, acc, tx, ty);
        __syncthreads();
    }
    #pragma unroll
    for (int i = 0; i < 8; i++) {
        int m = m0 + ty * 8 + i;
        size_t rowoff = (size_t)m * EMBED;
        #pragma unroll
        for (int j = 0; j < 4; j++) {
            float x0, x1;
            unpack2(acc[i][j], x0, x1);
            int n = n0 + tx * 8 + j * 2;
            g_y[rowoff + n]     = x0 + bo[n]     + g_emb[rowoff + n];
            g_y[rowoff + n + 1] = x1 + bo[n + 1] + g_emb[rowoff + n + 1];
        }
    }
}

// ---------------- prepass: split y -> A'' = [hi | lo | hi] bf16 ----------------
__global__ void __launch_bounds__(256) conv_y_kernel()
{
    int idx = blockIdx.x * 256 + threadIdx.x;        // 0 .. 4096*1024-1
    int row = idx >> 10;
    int k   = idx & 1023;
    float v = g_y[idx];
    __nv_bfloat16 h = __float2bfloat16_rn(v);
    __nv_bfloat16 l = __float2bfloat16_rn(v - __bfloat162float(h));
    size_t base = (size_t)row * K_EFF;
    g_A2[base + k]        = h;
    g_A2[base + 1024 + k] = l;
    g_A2[base + 2048 + k] = h;
}

// ---------------- prepass: transpose+split Wu -> B'' = [hi | hi | lo] (K-major) ----------------
__global__ void __launch_bounds__(256) conv_wu_kernel(const float* __restrict__ Wu)
{
    __shared__ float t[32][33];
    int n0 = blockIdx.x * 32;
    int k0 = blockIdx.y * 32;
    int tx = threadIdx.x, ty = threadIdx.y;          // 32 x 8
    #pragma unroll
    for (int i = 0; i < 4; i++) {
        int k = k0 + ty + i * 8;
        int n = n0 + tx;
        t[ty + i * 8][tx] = (n < VOCAB) ? Wu[(size_t)k * VOCAB + n] : 0.f;
    }
    __syncthreads();
    #pragma unroll
    for (int i = 0; i < 4; i++) {
        int n = n0 + ty + i * 8;
        int k = k0 + tx;
        float v = t[tx][ty + i * 8];
        __nv_bfloat16 h = __float2bfloat16_rn(v);
        __nv_bfloat16 l = __float2bfloat16_rn(v - __bfloat162float(h));
        size_t base = (size_t)n * K_EFF;
        g_B2[base + k]        = h;
        g_B2[base + 1024 + k] = h;
        g_B2[base + 2048 + k] = l;
    }
}

// ---------------- logits GEMM on HMMA (mma.sync bf16) ----------------
// CTA 128x128, 8 warps in 2(m) x 4(n), warp tile 64x32, k-step 32.
// SMEM tiles: 128 rows x 32 bf16 = 64B/row, XOR swizzle (chunk ^ ((row>>1)&3)).
// NOTE: out rows have stride VOCAB=50257 floats (odd) -> odd rows are only
// 4-byte aligned. Epilogue stores MUST be scalar 32-bit.
__global__ void __launch_bounds__(256, 2) wu_mma_kernel(const float* __restrict__ bu,
                                                        float* __restrict__ out)
{
    __shared__ __align__(128) unsigned char sAb[2][8192];
    __shared__ __align__(128) unsigned char sBb[2][8192];
    const int tid  = threadIdx.x;
    const int lane = tid & 31;
    const int wid  = tid >> 5;
    const int m0 = blockIdx.x * 128;
    const int n0 = blockIdx.y * 128;
    const int wm = (wid & 1) * 64;     // warp m offset in CTA tile
    const int wn = (wid >> 1) * 32;    // warp n offset in CTA tile

    float acc[4][4][4];
    #pragma unroll
    for (int i = 0; i < 4; i++)
        #pragma unroll
        for (int j = 0; j < 4; j++)
            #pragma unroll
            for (int r = 0; r < 4; r++) acc[i][j][r] = 0.f;

    const __nv_bfloat16* Ab = g_A2 + (size_t)m0 * K_EFF;
    const __nv_bfloat16* Bb = g_B2 + (size_t)n0 * K_EFF;

    // per-thread cp.async chunk coords (2 chunks each for A and B)
    // chunk id c in [0,512): row = c>>2, k-chunk = c&3 (8 bf16 = 16B each)
    int r0 = tid >> 2,          ck0 = tid & 3;
    int r1 = (tid + 256) >> 2,  ck1 = (tid + 256) & 3;
    uint32_t off0 = r0 * 64 + ((ck0 ^ ((r0 >> 1) & 3)) << 4);
    uint32_t off1 = r1 * 64 + ((ck1 ^ ((r1 >> 1) & 3)) << 4);
    size_t src0 = (size_t)r0 * K_EFF + ck0 * 8;
    size_t src1 = (size_t)r1 * K_EFF + ck1 * 8;
    uint32_t sa[2] = { smem_u32(sAb[0]), smem_u32(sAb[1]) };
    uint32_t sb[2] = { smem_u32(sBb[0]), smem_u32(sBb[1]) };

    // prologue: load k-step 0 into buffer 0
    cp16(sa[0] + off0, Ab + src0);
    cp16(sa[0] + off1, Ab + src1);
    cp16(sb[0] + off0, Bb + src0);
    cp16(sb[0] + off1, Bb + src1);
    CP_COMMIT();

    // ldmatrix lane-address components
    const int a_r8 = (lane & 7) + ((lane >> 3) & 1) * 8;  // row within m16
    const int a_kh = (lane >> 4) * 8;                     // k half offset
    const int b_r8 = (lane & 7) + (lane >> 4) * 8;        // row within n16
    const int b_kh = ((lane >> 3) & 1) * 8;

    for (int kt = 0; kt < WU_NK; kt++) {
        if (kt + 1 < WU_NK) {
            int nb = (kt + 1) & 1;
            const __nv_bfloat16* Ak = Ab + (size_t)(kt + 1) * 32;
            const __nv_bfloat16* Bk = Bb + (size_t)(kt + 1) * 32;
            cp16(sa[nb] + off0, Ak + src0);
            cp16(sa[nb] + off1, Ak + src1);
            cp16(sb[nb] + off0, Bk + src0);
            cp16(sb[nb] + off1, Bk + src1);
            CP_COMMIT();
            CP_WAIT(1);
        } else {
            CP_WAIT(0);
        }
        __syncthreads();

        const uint32_t A0 = sa[kt & 1];
        const uint32_t B0 = sb[kt & 1];
        #pragma unroll
        for (int ks = 0; ks < 32; ks += 16) {
            uint32_t af[4][4], bf[4][2];
            #pragma unroll
            for (int mi = 0; mi < 4; mi++) {
                int row = wm + mi * 16 + a_r8;
                int kk  = ks + a_kh;
                uint32_t addr = A0 + row * 64 + (((kk >> 3) ^ ((row >> 1) & 3)) << 4);
                ldm_x4(af[mi], addr);
            }
            #pragma unroll
            for (int nj = 0; nj < 2; nj++) {
                int row = wn + nj * 16 + b_r8;
                int kk  = ks + b_kh;
                uint32_t addr = B0 + row * 64 + (((kk >> 3) ^ ((row >> 1) & 3)) << 4);
                uint32_t t[4];
                ldm_x4(t, addr);
                bf[nj * 2][0]     = t[0]; bf[nj * 2][1]     = t[1];
                bf[nj * 2 + 1][0] = t[2]; bf[nj * 2 + 1][1] = t[3];
            }
            #pragma unroll
            for (int mi = 0; mi < 4; mi++)
                #pragma unroll
                for (int nj = 0; nj < 4; nj++)
                    mma_bf16(acc[mi][nj], af[mi], bf[nj][0], bf[nj][1]);
        }
        __syncthreads();
    }

    // epilogue: acc[mi][nj]: d0,d1 -> (row = l/4, cols 2(l%4),+1); d2,d3 -> row+8
    // scalar stores only (odd row stride of `out`)
    const int er = lane >> 2;
    const int ec = (lane & 3) * 2;
    #pragma unroll
    for (int mi = 0; mi < 4; mi++) {
        #pragma unroll
        for (int nj = 0; nj < 4; nj++) {
            int col = n0 + wn + nj * 8 + ec;
            float b0v = (col < VOCAB)     ? __ldg(bu + col)     : 0.f;
            float b1v = (col + 1 < VOCAB) ? __ldg(bu + col + 1) : 0.f;
            int row = m0 + wm + mi * 16 + er;
            float* p0 = out + (size_t)row * VOCAB + col;
            float* p1 = out + (size_t)(row + 8) * VOCAB + col;
            if (col < VOCAB) {
                p0[0] = acc[mi][nj][0] + b0v;
                p1[0] = acc[mi][nj][2] + b0v;
            }
            if (col + 1 < VOCAB) {
                p0[1] = acc[mi][nj][1] + b1v;
                p1[1] = acc[mi][nj][3] + b1v;
            }
        }
    }
}

// ---------------- launch ----------------
extern "C" void kernel_launch(void* const* d_in, const int* in_sizes, int n_in,
                              void* d_out, int out_size)
{
    const int*   x  = (const int*)  d_in[0];
    const float* E  = (const float*)d_in[1];
    const float* pe = (const float*)d_in[2];
    const float* Wq = (const float*)d_in[3];
    const float* bq = (const float*)d_in[4];
    const float* Wk = (const float*)d_in[5];
    const float* bk = (const float*)d_in[6];
    const float* Wv = (const float*)d_in[7];
    const float* bv = (const float*)d_in[8];
    const float* Wo = (const float*)d_in[9];
    const float* bo = (const float*)d_in[10];
    const float* Wu = (const float*)d_in[11];
    const float* bu = (const float*)d_in[12];
    float* out = (float*)d_out;

    embed_kernel<<<4096, 256>>>(x, E, pe);

    dim3 gq(M_TOT / 128, EMBED / 128);
    qkv_gemm<<<gq, 256>>>(Wq, bq, 0);
    qkv_gemm<<<gq, 256>>>(Wk, bk, 1);
    qkv_gemm<<<gq, 256>>>(Wv, bv, 2);

    // Wu transpose/split does not depend on y -> overlaps with the attention path
    conv_wu_kernel<<<dim3(N_PAD / 32, EMBED / 32), dim3(32, 8)>>>(Wu);

    attn_kernel<<<BATCH * NHEAD, 256>>>();

    wo_gemm<<<dim3(M_TOT / 128, EMBED / 128), 256>>>(Wo, bo);

    conv_y_kernel<<<(M_TOT * EMBED) / 256, 256>>>();

    wu_mma_kernel<<<dim3(M_TOT / 128, N_PAD / 128), 256>>>(bu, out);
}

// round 9
// speedup vs baseline: 2.9504x; 1.1525x over previous
#include <cuda_runtime.h>
#include <cuda_bf16.h>
#include <cstdint>

#define BATCH 64
#define SEQ   64
#define EMBED 1024
#define NHEAD 16
#define HDIM  64
#define VOCAB 50257
#define M_TOT (BATCH*SEQ)   /* 4096 */

#define N_PAD  50304        /* 393*128 */
#define K_EFF  3072         /* 3 x 1024 split sections */
#define NK_IT  48           /* K_EFF / 64 */

// ---------------- scratch (no allocation allowed) ----------------
__device__ float g_emb[M_TOT*EMBED];
__device__ float g_q  [M_TOT*EMBED];
__device__ float g_k  [M_TOT*EMBED];
__device__ float g_v  [M_TOT*EMBED];
__device__ float g_cat[M_TOT*EMBED];
// split-bf16 operands (A = [hi|lo|hi], B = [hi|hi|lo], K-major, stride K_EFF)
__device__ __align__(16) __nv_bfloat16 g_A2  [(size_t)M_TOT * K_EFF];   // emb-split, then cat-split
__device__ __align__(16) __nv_bfloat16 g_A3  [(size_t)M_TOT * K_EFF];   // y-split
__device__ __align__(16) __nv_bfloat16 g_Bqkv[(size_t)3072  * K_EFF];   // [Wq|Wk|Wv] split
__device__ __align__(16) __nv_bfloat16 g_Bwo [(size_t)EMBED * K_EFF];   // Wo split
__device__ __align__(16) __nv_bfloat16 g_B2  [(size_t)N_PAD * K_EFF];   // Wu split

// ---------------- helpers ----------------
__device__ __forceinline__ uint32_t smem_u32(const void* p) {
    uint32_t a;
    asm("{ .reg .u64 t; cvta.to.shared.u64 t, %1; cvt.u32.u64 %0, t; }" : "=r"(a) : "l"(p));
    return a;
}
__device__ __forceinline__ void cp16(uint32_t dst, const void* src) {
    asm volatile("cp.async.cg.shared.global [%0], [%1], 16;" :: "r"(dst), "l"(src) : "memory");
}
#define CP_COMMIT() asm volatile("cp.async.commit_group;" ::: "memory")
#define CP_WAIT(N)  asm volatile("cp.async.wait_group %0;" :: "n"(N) : "memory")

__device__ __forceinline__ void ldm_x4(uint32_t (&r)[4], uint32_t addr) {
    asm volatile("ldmatrix.sync.aligned.m8n8.x4.shared.b16 {%0,%1,%2,%3}, [%4];"
        : "=r"(r[0]), "=r"(r[1]), "=r"(r[2]), "=r"(r[3]) : "r"(addr));
}
__device__ __forceinline__ void mma_bf16(float (&d)[4], const uint32_t (&a)[4],
                                         uint32_t b0, uint32_t b1) {
    asm volatile("mma.sync.aligned.m16n8k16.row.col.f32.bf16.bf16.f32 "
        "{%0,%1,%2,%3}, {%4,%5,%6,%7}, {%8,%9}, {%0,%1,%2,%3};"
        : "+f"(d[0]), "+f"(d[1]), "+f"(d[2]), "+f"(d[3])
        : "r"(a[0]), "r"(a[1]), "r"(a[2]), "r"(a[3]), "r"(b0), "r"(b1));
}
__device__ __forceinline__ __nv_bfloat162 split_hi2(float a, float b, __nv_bfloat162& lo) {
    __nv_bfloat16 ha = __float2bfloat16_rn(a);
    __nv_bfloat16 hb = __float2bfloat16_rn(b);
    lo = __nv_bfloat162(__float2bfloat16_rn(a - __bfloat162float(ha)),
                        __float2bfloat16_rn(b - __bfloat162float(hb)));
    return __nv_bfloat162(ha, hb);
}

// ================= shared HMMA mainloop =================
// CTA tile 128(m) x 128(n), K_EFF = 3072, k-chunk 64 per stage, 3-stage cp.async ring.
// Stage layout (32KB): A [2 sub][128 rows][32 bf16 (64B, XOR swizzled)], B same at +16KB.
#define STG_SZ 32768

__device__ __forceinline__ void fill_stage(uint32_t sbase, const __nv_bfloat16* Ab,
                                           const __nv_bfloat16* Bb, int kt, int tid)
{
    #pragma unroll
    for (int i = 0; i < 4; i++) {
        int c = tid + i * 256;                 // 0..1023
        int row = c >> 3, ck = c & 7;
        uint32_t off = (ck >> 2) * 8192 + row * 64 + (((ck & 3) ^ ((row >> 1) & 3)) << 4);
        cp16(sbase + off, Ab + (size_t)row * K_EFF + kt * 64 + ck * 8);
    }
    #pragma unroll
    for (int i = 0; i < 4; i++) {
        int c = tid + i * 256;
        int row = c >> 3, ck = c & 7;
        uint32_t off = 16384 + (ck >> 2) * 8192 + row * 64 + (((ck & 3) ^ ((row >> 1) & 3)) << 4);
        cp16(sbase + off, Bb + (size_t)row * K_EFF + kt * 64 + ck * 8);
    }
}

__device__ __forceinline__ void compute_stage(uint32_t sbase, float (&acc)[4][4][4],
                                              int lane, int wm, int wn)
{
    const int a_r8 = (lane & 7) + ((lane >> 3) & 1) * 8;
    const int a_kh = (lane >> 4) * 8;
    const int b_r8 = (lane & 7) + (lane >> 4) * 8;
    const int b_kh = ((lane >> 3) & 1) * 8;
    #pragma unroll
    for (int sub = 0; sub < 2; sub++) {
        const uint32_t A0 = sbase + sub * 8192;
        const uint32_t B0 = sbase + 16384 + sub * 8192;
        #pragma unroll
        for (int ks = 0; ks < 32; ks += 16) {
            uint32_t af[4][4], bf[4][2];
            #pragma unroll
            for (int mi = 0; mi < 4; mi++) {
                int row = wm + mi * 16 + a_r8;
                int kk  = ks + a_kh;
                ldm_x4(af[mi], A0 + row * 64 + (((kk >> 3) ^ ((row >> 1) & 3)) << 4));
            }
            #pragma unroll
            for (int nj = 0; nj < 2; nj++) {
                int row = wn + nj * 16 + b_r8;
                int kk  = ks + b_kh;
                uint32_t t[4];
                ldm_x4(t, B0 + row * 64 + (((kk >> 3) ^ ((row >> 1) & 3)) << 4));
                bf[nj * 2][0]     = t[0]; bf[nj * 2][1]     = t[1];
                bf[nj * 2 + 1][0] = t[2]; bf[nj * 2 + 1][1] = t[3];
            }
            #pragma unroll
            for (int mi = 0; mi < 4; mi++)
                #pragma unroll
                for (int nj = 0; nj < 4; nj++)
                    mma_bf16(acc[mi][nj], af[mi], bf[nj][0], bf[nj][1]);
        }
    }
}

__device__ __forceinline__ void hmma_loop(const __nv_bfloat16* Ab, const __nv_bfloat16* Bb,
                                          char* sm, float (&acc)[4][4][4],
                                          int tid, int lane, int wm, int wn)
{
    #pragma unroll
    for (int i = 0; i < 4; i++)
        #pragma unroll
        for (int j = 0; j < 4; j++)
            #pragma unroll
            for (int r = 0; r < 4; r++) acc[i][j][r] = 0.f;

    const uint32_t sb = smem_u32(sm);
    fill_stage(sb,           Ab, Bb, 0, tid); CP_COMMIT();
    fill_stage(sb + STG_SZ,  Ab, Bb, 1, tid); CP_COMMIT();

    for (int kt = 0; kt < NK_IT; kt++) {
        CP_WAIT(1);                 // in-order completion: group kt is done
        __syncthreads();            // data visible; also guards ring reuse (WAR)
        if (kt + 2 < NK_IT)
            fill_stage(sb + ((kt + 2) % 3) * STG_SZ, Ab, Bb, kt + 2, tid);
        CP_COMMIT();                // keep one group per iter (empty ok)
        compute_stage(sb + (kt % 3) * STG_SZ, acc, lane, wm, wn);
    }
}

// ---------------- embed (+ fused emb-split into g_A2) ----------------
__global__ void __launch_bounds__(256) embed_kernel(const int* __restrict__ x,
                                                    const float* __restrict__ E,
                                                    const float* __restrict__ pe)
{
    int idx = blockIdx.x * 256 + threadIdx.x;
    int row = idx >> 8;
    int c   = (idx & 255) << 2;
    int tok = x[row];
    float4 e = *(const float4*)(E  + (size_t)tok * EMBED + c);
    float4 p = *(const float4*)(pe + (size_t)(row & 63) * EMBED + c);
    e.x += p.x; e.y += p.y; e.z += p.z; e.w += p.w;
    *(float4*)(g_emb + (size_t)row * EMBED + c) = e;

    __nv_bfloat162 l01, l23;
    __nv_bfloat162 h01 = split_hi2(e.x, e.y, l01);
    __nv_bfloat162 h23 = split_hi2(e.z, e.w, l23);
    size_t base = (size_t)row * K_EFF;
    *(__nv_bfloat162*)(g_A2 + base + c)            = h01;
    *(__nv_bfloat162*)(g_A2 + base + c + 2)        = h23;
    *(__nv_bfloat162*)(g_A2 + base + 1024 + c)     = l01;
    *(__nv_bfloat162*)(g_A2 + base + 1024 + c + 2) = l23;
    *(__nv_bfloat162*)(g_A2 + base + 2048 + c)     = h01;
    *(__nv_bfloat162*)(g_A2 + base + 2048 + c + 2) = h23;
}

// ---------------- weight split prepasses ----------------
// Wq/Wk/Wv: [H][D][hd] -> g_Bqkv[z*1024 + n][k] with n = h*64+e, B-split [hi|hi|lo]
__global__ void __launch_bounds__(256) conv_w_qkv(const float* __restrict__ Wq,
                                                  const float* __restrict__ Wk,
                                                  const float* __restrict__ Wv)
{
    __shared__ float t[32][33];
    const float* W = (blockIdx.z == 0) ? Wq : (blockIdx.z == 1) ? Wk : Wv;
    int n0 = blockIdx.x * 32;                 // n within weight (0..1023)
    int k0 = blockIdx.y * 32;
    int tx = threadIdx.x, ty = threadIdx.y;   // 32 x 8
    int h  = n0 >> 6, e0 = n0 & 63;
    #pragma unroll
    for (int i = 0; i < 4; i++) {
        int kk = ty + i * 8;
        t[kk][tx] = W[(size_t)h * (EMBED * HDIM) + (size_t)(k0 + kk) * HDIM + e0 + tx];
    }
    __syncthreads();
    #pragma unroll
    for (int i = 0; i < 4; i++) {
        int nn = ty + i * 8;
        int k  = k0 + tx;
        float v = t[tx][nn];
        __nv_bfloat16 hB = __float2bfloat16_rn(v);
        __nv_bfloat16 lB = __float2bfloat16_rn(v - __bfloat162float(hB));
        size_t base = (size_t)(blockIdx.z * 1024 + n0 + nn) * K_EFF;
        g_Bqkv[base + k]        = hB;
        g_Bqkv[base + 1024 + k] = hB;
        g_Bqkv[base + 2048 + k] = lB;
    }
}

// Wo: [1024 k][1024 n] row-major -> g_Bwo[n][k], split [hi|hi|lo]
__global__ void __launch_bounds__(256) conv_w_o(const float* __restrict__ Wo)
{
    __shared__ float t[32][33];
    int n0 = blockIdx.x * 32;
    int k0 = blockIdx.y * 32;
    int tx = threadIdx.x, ty = threadIdx.y;
    #pragma unroll
    for (int i = 0; i < 4; i++) {
        int kk = ty + i * 8;
        t[kk][tx] = Wo[(size_t)(k0 + kk) * EMBED + n0 + tx];
    }
    __syncthreads();
    #pragma unroll
    for (int i = 0; i < 4; i++) {
        int nn = ty + i * 8;
        int k  = k0 + tx;
        float v = t[tx][nn];
        __nv_bfloat16 hB = __float2bfloat16_rn(v);
        __nv_bfloat16 lB = __float2bfloat16_rn(v - __bfloat162float(hB));
        size_t base = (size_t)(n0 + nn) * K_EFF;
        g_Bwo[base + k]        = hB;
        g_Bwo[base + 1024 + k] = hB;
        g_Bwo[base + 2048 + k] = lB;
    }
}

// Wu: [1024 k][VOCAB n] (odd stride -> scalar loads) -> g_B2[n][k], split [hi|hi|lo]
__global__ void __launch_bounds__(256) conv_wu_kernel(const float* __restrict__ Wu)
{
    __shared__ float t[32][33];
    int n0 = blockIdx.x * 32;
    int k0 = blockIdx.y * 32;
    int tx = threadIdx.x, ty = threadIdx.y;
    #pragma unroll
    for (int i = 0; i < 4; i++) {
        int k = k0 + ty + i * 8;
        int n = n0 + tx;
        t[ty + i * 8][tx] = (n < VOCAB) ? Wu[(size_t)k * VOCAB + n] : 0.f;
    }
    __syncthreads();
    #pragma unroll
    for (int i = 0; i < 4; i++) {
        int n = n0 + ty + i * 8;
        int k = k0 + tx;
        float v = t[tx][ty + i * 8];
        __nv_bfloat16 h = __float2bfloat16_rn(v);
        __nv_bfloat16 l = __float2bfloat16_rn(v - __bfloat162float(h));
        size_t base = (size_t)n * K_EFF;
        g_B2[base + k]        = h;
        g_B2[base + 1024 + k] = h;
        g_B2[base + 2048 + k] = l;
    }
}

// ---------------- cat -> split (g_A2 reuse) ----------------
__global__ void __launch_bounds__(256) conv_cat_kernel()
{
    int idx = blockIdx.x * 256 + threadIdx.x;    // float4 index
    int row = idx >> 8;
    int c   = (idx & 255) << 2;
    float4 v = *(const float4*)(g_cat + (size_t)row * EMBED + c);
    __nv_bfloat162 l01, l23;
    __nv_bfloat162 h01 = split_hi2(v.x, v.y, l01);
    __nv_bfloat162 h23 = split_hi2(v.z, v.w, l23);
    size_t base = (size_t)row * K_EFF;
    *(__nv_bfloat162*)(g_A2 + base + c)            = h01;
    *(__nv_bfloat162*)(g_A2 + base + c + 2)        = h23;
    *(__nv_bfloat162*)(g_A2 + base + 1024 + c)     = l01;
    *(__nv_bfloat162*)(g_A2 + base + 1024 + c + 2) = l23;
    *(__nv_bfloat162*)(g_A2 + base + 2048 + c)     = h01;
    *(__nv_bfloat162*)(g_A2 + base + 2048 + c + 2) = h23;
}

// ---------------- attention (fp32, unchanged) ----------------
__global__ void __launch_bounds__(256) attn_kernel()
{
    __shared__ float sQ [64][68];
    __shared__ float sKV[64][68];
    int bh  = blockIdx.x;
    int tid = threadIdx.x;
    const float* qb = g_q + (size_t)bh * (SEQ * HDIM);
    const float* kb = g_k + (size_t)bh * (SEQ * HDIM);
    const float* vb = g_v + (size_t)bh * (SEQ * HDIM);
    #pragma unroll
    for (int i = 0; i < 4; i++) {
        int idx = tid + i * 256;
        int r = idx >> 4, c = (idx & 15) << 2;
        *(float4*)(&sQ [r][c]) = *(const float4*)(qb + r * 64 + c);
        *(float4*)(&sKV[r][c]) = *(const float4*)(kb + r * 64 + c);
    }
    __syncthreads();

    int s = tid >> 2, q = tid & 3;
    float4 qv[16];
    #pragma unroll
    for (int k4 = 0; k4 < 16; k4++) qv[k4] = *(const float4*)(&sQ[s][k4 * 4]);

    float sc[16];
    #pragma unroll
    for (int j = 0; j < 16; j++) {
        int t = q + 4 * j;
        float d = 0.f;
        #pragma unroll
        for (int k4 = 0; k4 < 16; k4++) {
            float4 kv = *(const float4*)(&sKV[t][k4 * 4]);
            d += qv[k4].x * kv.x + qv[k4].y * kv.y + qv[k4].z * kv.z + qv[k4].w * kv.w;
        }
        sc[j] = (t <= s) ? d * 0.125f : -1e30f;
    }
    float mx = sc[0];
    #pragma unroll
    for (int j = 1; j < 16; j++) mx = fmaxf(mx, sc[j]);
    mx = fmaxf(mx, __shfl_xor_sync(0xFFFFFFFFu, mx, 1));
    mx = fmaxf(mx, __shfl_xor_sync(0xFFFFFFFFu, mx, 2));
    float sum = 0.f;
    #pragma unroll
    for (int j = 0; j < 16; j++) { sc[j] = __expf(sc[j] - mx); sum += sc[j]; }
    sum += __shfl_xor_sync(0xFFFFFFFFu, sum, 1);
    sum += __shfl_xor_sync(0xFFFFFFFFu, sum, 2);
    float inv = 1.f / sum;
    #pragma unroll
    for (int j = 0; j < 16; j++) sc[j] *= inv;

    __syncthreads();
    #pragma unroll
    for (int i = 0; i < 4; i++) {
        int idx = tid + i * 256;
        int r = idx >> 4, c = (idx & 15) << 2;
        *(float4*)(&sKV[r][c]) = *(const float4*)(vb + r * 64 + c);
    }
    __syncthreads();

    float po[64];
    #pragma unroll
    for (int e = 0; e < 64; e++) po[e] = 0.f;
    #pragma unroll
    for (int j = 0; j < 16; j++) {
        int t = q + 4 * j;
        float w = sc[j];
        #pragma unroll
        for (int e4 = 0; e4 < 16; e4++) {
            float4 v = *(const float4*)(&sKV[t][e4 * 4]);
            po[e4 * 4 + 0] += w * v.x;
            po[e4 * 4 + 1] += w * v.y;
            po[e4 * 4 + 2] += w * v.z;
            po[e4 * 4 + 3] += w * v.w;
        }
    }
    #pragma unroll
    for (int e = 0; e < 64; e++) {
        po[e] += __shfl_xor_sync(0xFFFFFFFFu, po[e], 1);
        po[e] += __shfl_xor_sync(0xFFFFFFFFu, po[e], 2);
    }
    int b = bh >> 4, h = bh & 15;
    float* dst = g_cat + (size_t)b * (SEQ * EMBED) + (size_t)s * EMBED + h * HDIM + q * 16;
    #pragma unroll
    for (int i = 0; i < 4; i++) {
        int e0 = q * 16 + i * 4;
        *(float4*)(dst + i * 4) = make_float4(po[e0], po[e0 + 1], po[e0 + 2], po[e0 + 3]);
    }
}

// ---------------- QKV on HMMA: [emb-split] @ [Wq|Wk|Wv]-split ----------------
__global__ void __launch_bounds__(256, 2) qkv_mma(const float* __restrict__ bq,
                                                  const float* __restrict__ bk,
                                                  const float* __restrict__ bv)
{
    extern __shared__ char sm[];
    const int tid = threadIdx.x, lane = tid & 31, wid = tid >> 5;
    const int wm = (wid & 1) * 64, wn = (wid >> 1) * 32;
    const int m0 = blockIdx.x * 128;
    const int n0 = blockIdx.y * 128;     // global n in [0, 3072)

    float acc[4][4][4];
    hmma_loop(g_A2 + (size_t)m0 * K_EFF, g_Bqkv + (size_t)n0 * K_EFF,
              sm, acc, tid, lane, wm, wn);

    const int which = n0 >> 10;          // uniform per CTA
    float* outp = (which == 0) ? g_q : (which == 1) ? g_k : g_v;
    const float* bias = (which == 0) ? bq : (which == 1) ? bk : bv;

    const int er = lane >> 2;
    const int ec = (lane & 3) * 2;
    #pragma unroll
    for (int mi = 0; mi < 4; mi++) {
        #pragma unroll
        for (int nj = 0; nj < 4; nj++) {
            int col = n0 + wn + nj * 8 + ec;      // global
            int n   = col & 1023;                  // within weight
            int h = n >> 6, e = n & 63;
            float b0v = bias[n], b1v = bias[n + 1];
            int row0 = m0 + wm + mi * 16 + er;
            #pragma unroll
            for (int half = 0; half < 2; half++) {
                int row = row0 + half * 8;
                int b = row >> 6, s = row & 63;
                float* dst = outp + (size_t)(((b * NHEAD + h) * SEQ + s) * HDIM + e);
                *(float2*)dst = make_float2(acc[mi][nj][half * 2] + b0v,
                                            acc[mi][nj][half * 2 + 1] + b1v);
            }
        }
    }
}

// ---------------- Wo on HMMA: y = cat-split @ Wo-split + bo + emb; emit y-split ----------------
__global__ void __launch_bounds__(256, 2) wo_mma(const float* __restrict__ bo)
{
    extern __shared__ char sm[];
    const int tid = threadIdx.x, lane = tid & 31, wid = tid >> 5;
    const int wm = (wid & 1) * 64, wn = (wid >> 1) * 32;
    const int m0 = blockIdx.x * 128;
    const int n0 = blockIdx.y * 128;

    float acc[4][4][4];
    hmma_loop(g_A2 + (size_t)m0 * K_EFF, g_Bwo + (size_t)n0 * K_EFF,
              sm, acc, tid, lane, wm, wn);

    const int er = lane >> 2;
    const int ec = (lane & 3) * 2;
    #pragma unroll
    for (int mi = 0; mi < 4; mi++) {
        #pragma unroll
        for (int nj = 0; nj < 4; nj++) {
            int col = n0 + wn + nj * 8 + ec;
            float b0v = bo[col], b1v = bo[col + 1];
            int row0 = m0 + wm + mi * 16 + er;
            #pragma unroll
            for (int half = 0; half < 2; half++) {
                int row = row0 + half * 8;
                float2 em = *(const float2*)(g_emb + (size_t)row * EMBED + col);
                float y0 = acc[mi][nj][half * 2]     + b0v + em.x;
                float y1 = acc[mi][nj][half * 2 + 1] + b1v + em.y;
                __nv_bfloat162 lo;
                __nv_bfloat162 hi = split_hi2(y0, y1, lo);
                size_t base = (size_t)row * K_EFF + col;
                *(__nv_bfloat162*)(g_A3 + base)        = hi;
                *(__nv_bfloat162*)(g_A3 + base + 1024) = lo;
                *(__nv_bfloat162*)(g_A3 + base + 2048) = hi;
            }
        }
    }
}

// ---------------- logits on HMMA: out = y-split @ Wu-split + bu ----------------
// out rows have odd stride (VOCAB) -> scalar stores only.
__global__ void __launch_bounds__(256, 2) wu_mma(const float* __restrict__ bu,
                                                 float* __restrict__ out)
{
    extern __shared__ char sm[];
    const int tid = threadIdx.x, lane = tid & 31, wid = tid >> 5;
    const int wm = (wid & 1) * 64, wn = (wid >> 1) * 32;
    const int m0 = blockIdx.x * 128;
    const int n0 = blockIdx.y * 128;

    float acc[4][4][4];
    hmma_loop(g_A3 + (size_t)m0 * K_EFF, g_B2 + (size_t)n0 * K_EFF,
              sm, acc, tid, lane, wm, wn);

    const int er = lane >> 2;
    const int ec = (lane & 3) * 2;
    #pragma unroll
    for (int mi = 0; mi < 4; mi++) {
        #pragma unroll
        for (int nj = 0; nj < 4; nj++) {
            int col = n0 + wn + nj * 8 + ec;
            float b0v = (col < VOCAB)     ? __ldg(bu + col)     : 0.f;
            float b1v = (col + 1 < VOCAB) ? __ldg(bu + col + 1) : 0.f;
            int row = m0 + wm + mi * 16 + er;
            float* p0 = out + (size_t)row * VOCAB + col;
            float* p1 = out + (size_t)(row + 8) * VOCAB + col;
            if (col < VOCAB) {
                p0[0] = acc[mi][nj][0] + b0v;
                p1[0] = acc[mi][nj][2] + b0v;
            }
            if (col + 1 < VOCAB) {
                p0[1] = acc[mi][nj][1] + b1v;
                p1[1] = acc[mi][nj][3] + b1v;
            }
        }
    }
}

// ---------------- launch ----------------
#define MMA_SMEM (3 * STG_SZ)   /* 98304 */

extern "C" void kernel_launch(void* const* d_in, const int* in_sizes, int n_in,
                              void* d_out, int out_size)
{
    const int*   x  = (const int*)  d_in[0];
    const float* E  = (const float*)d_in[1];
    const float* pe = (const float*)d_in[2];
    const float* Wq = (const float*)d_in[3];
    const float* bq = (const float*)d_in[4];
    const float* Wk = (const float*)d_in[5];
    const float* bk = (const float*)d_in[6];
    const float* Wv = (const float*)d_in[7];
    const float* bv = (const float*)d_in[8];
    const float* Wo = (const float*)d_in[9];
    const float* bo = (const float*)d_in[10];
    const float* Wu = (const float*)d_in[11];
    const float* bu = (const float*)d_in[12];
    float* out = (float*)d_out;

    cudaFuncSetAttribute(qkv_mma, cudaFuncAttributeMaxDynamicSharedMemorySize, MMA_SMEM);
    cudaFuncSetAttribute(wo_mma,  cudaFuncAttributeMaxDynamicSharedMemorySize, MMA_SMEM);
    cudaFuncSetAttribute(wu_mma,  cudaFuncAttributeMaxDynamicSharedMemorySize, MMA_SMEM);

    embed_kernel<<<4096, 256>>>(x, E, pe);                              // emb + emb-split
    conv_w_qkv<<<dim3(32, 32, 3), dim3(32, 8)>>>(Wq, Wk, Wv);           // weight splits
    conv_w_o  <<<dim3(32, 32),    dim3(32, 8)>>>(Wo);
    conv_wu_kernel<<<dim3(N_PAD / 32, EMBED / 32), dim3(32, 8)>>>(Wu);

    qkv_mma<<<dim3(32, 24), 256, MMA_SMEM>>>(bq, bk, bv);               // q,k,v

    attn_kernel<<<BATCH * NHEAD, 256>>>();                              // -> cat

    conv_cat_kernel<<<4096, 256>>>();                                   // cat-split -> g_A2
    wo_mma<<<dim3(32, 8), 256, MMA_SMEM>>>(bo);                         // y-split -> g_A3

    wu_mma<<<dim3(32, N_PAD / 128), 256, MMA_SMEM>>>(bu, out);          // logits
}

// round 10
// speedup vs baseline: 4.2822x; 1.4514x over previous
#include <cuda_runtime.h>
#include <cuda_fp16.h>
#include <cstdint>

#define BATCH 64
#define SEQ   64
#define EMBED 1024
#define NHEAD 16
#define HDIM  64
#define VOCAB 50257
#define M_TOT (BATCH*SEQ)   /* 4096 */

#define N_PAD  50304        /* 393*128 */
#define K_EFF  2048         /* A sections: [hi | lo] fp16 */
#define KB_DIM 1024         /* B is single fp16 section; mainloop repeats it */
#define NK_IT  32           /* K_EFF / 64 */

// ---------------- scratch (no allocation allowed) ----------------
__device__ float g_emb[M_TOT*EMBED];
__device__ float g_q  [M_TOT*EMBED];
__device__ float g_k  [M_TOT*EMBED];
__device__ float g_v  [M_TOT*EMBED];
__device__ float g_cat[M_TOT*EMBED];
// split-fp16 operands: A = [hi|lo] (stride K_EFF), B = fp16(W) (stride KB_DIM, K-major)
__device__ __align__(16) __half g_A2  [(size_t)M_TOT * K_EFF];    // emb-split, then cat-split
__device__ __align__(16) __half g_A3  [(size_t)M_TOT * K_EFF];    // y-split
__device__ __align__(16) __half g_Bqkv[(size_t)3072  * KB_DIM];   // [Wq|Wk|Wv]
__device__ __align__(16) __half g_Bwo [(size_t)EMBED * KB_DIM];   // Wo
__device__ __align__(16) __half g_B2  [(size_t)N_PAD * KB_DIM];   // Wu

// ---------------- helpers ----------------
__device__ __forceinline__ uint32_t smem_u32(const void* p) {
    uint32_t a;
    asm("{ .reg .u64 t; cvta.to.shared.u64 t, %1; cvt.u32.u64 %0, t; }" : "=r"(a) : "l"(p));
    return a;
}
__device__ __forceinline__ void cp16(uint32_t dst, const void* src) {
    asm volatile("cp.async.cg.shared.global [%0], [%1], 16;" :: "r"(dst), "l"(src) : "memory");
}
#define CP_COMMIT() asm volatile("cp.async.commit_group;" ::: "memory")
#define CP_WAIT(N)  asm volatile("cp.async.wait_group %0;" :: "n"(N) : "memory")

__device__ __forceinline__ void ldm_x4(uint32_t (&r)[4], uint32_t addr) {
    asm volatile("ldmatrix.sync.aligned.m8n8.x4.shared.b16 {%0,%1,%2,%3}, [%4];"
        : "=r"(r[0]), "=r"(r[1]), "=r"(r[2]), "=r"(r[3]) : "r"(addr));
}
__device__ __forceinline__ void mma_f16(float (&d)[4], const uint32_t (&a)[4],
                                        uint32_t b0, uint32_t b1) {
    asm volatile("mma.sync.aligned.m16n8k16.row.col.f32.f16.f16.f32 "
        "{%0,%1,%2,%3}, {%4,%5,%6,%7}, {%8,%9}, {%0,%1,%2,%3};"
        : "+f"(d[0]), "+f"(d[1]), "+f"(d[2]), "+f"(d[3])
        : "r"(a[0]), "r"(a[1]), "r"(a[2]), "r"(a[3]), "r"(b0), "r"(b1));
}
__device__ __forceinline__ __half2 split_hi2(float a, float b, __half2& lo) {
    __half ha = __float2half_rn(a);
    __half hb = __float2half_rn(b);
    lo = __half2(__float2half_rn(a - __half2float(ha)),
                 __float2half_rn(b - __half2float(hb)));
    return __half2(ha, hb);
}

// ================= shared HMMA mainloop =================
// CTA tile 128(m) x 128(n). A: K_EFF=2048 (hi|lo), B: KB_DIM=1024 repeated (kt & 15).
// k-chunk 64 per stage, 3-stage cp.async ring.
// Stage layout (32KB): A [2 sub][128 rows][32 fp16 (64B, XOR swizzled)], B same at +16KB.
#define STG_SZ 32768

__device__ __forceinline__ void fill_stage(uint32_t sbase, const __half* Ab,
                                           const __half* Bb, int kt, int tid)
{
    const int ka = kt * 64;
    const int kb = (kt & 15) * 64;
    #pragma unroll
    for (int i = 0; i < 4; i++) {
        int c = tid + i * 256;                 // 0..1023
        int row = c >> 3, ck = c & 7;
        uint32_t off = (ck >> 2) * 8192 + row * 64 + (((ck & 3) ^ ((row >> 1) & 3)) << 4);
        cp16(sbase + off, Ab + (size_t)row * K_EFF + ka + ck * 8);
    }
    #pragma unroll
    for (int i = 0; i < 4; i++) {
        int c = tid + i * 256;
        int row = c >> 3, ck = c & 7;
        uint32_t off = 16384 + (ck >> 2) * 8192 + row * 64 + (((ck & 3) ^ ((row >> 1) & 3)) << 4);
        cp16(sbase + off, Bb + (size_t)row * KB_DIM + kb + ck * 8);
    }
}

__device__ __forceinline__ void compute_stage(uint32_t sbase, float (&acc)[4][4][4],
                                              int lane, int wm, int wn)
{
    const int a_r8 = (lane & 7) + ((lane >> 3) & 1) * 8;
    const int a_kh = (lane >> 4) * 8;
    const int b_r8 = (lane & 7) + (lane >> 4) * 8;
    const int b_kh = ((lane >> 3) & 1) * 8;
    #pragma unroll
    for (int sub = 0; sub < 2; sub++) {
        const uint32_t A0 = sbase + sub * 8192;
        const uint32_t B0 = sbase + 16384 + sub * 8192;
        #pragma unroll
        for (int ks = 0; ks < 32; ks += 16) {
            uint32_t af[4][4], bf[4][2];
            #pragma unroll
            for (int mi = 0; mi < 4; mi++) {
                int row = wm + mi * 16 + a_r8;
                int kk  = ks + a_kh;
                ldm_x4(af[mi], A0 + row * 64 + (((kk >> 3) ^ ((row >> 1) & 3)) << 4));
            }
            #pragma unroll
            for (int nj = 0; nj < 2; nj++) {
                int row = wn + nj * 16 + b_r8;
                int kk  = ks + b_kh;
                uint32_t t[4];
                ldm_x4(t, B0 + row * 64 + (((kk >> 3) ^ ((row >> 1) & 3)) << 4));
                bf[nj * 2][0]     = t[0]; bf[nj * 2][1]     = t[1];
                bf[nj * 2 + 1][0] = t[2]; bf[nj * 2 + 1][1] = t[3];
            }
            #pragma unroll
            for (int mi = 0; mi < 4; mi++)
                #pragma unroll
                for (int nj = 0; nj < 4; nj++)
                    mma_f16(acc[mi][nj], af[mi], bf[nj][0], bf[nj][1]);
        }
    }
}

__device__ __forceinline__ void hmma_loop(const __half* Ab, const __half* Bb,
                                          char* sm, float (&acc)[4][4][4],
                                          int tid, int lane, int wm, int wn)
{
    #pragma unroll
    for (int i = 0; i < 4; i++)
        #pragma unroll
        for (int j = 0; j < 4; j++)
            #pragma unroll
            for (int r = 0; r < 4; r++) acc[i][j][r] = 0.f;

    const uint32_t sb = smem_u32(sm);
    fill_stage(sb,          Ab, Bb, 0, tid); CP_COMMIT();
    fill_stage(sb + STG_SZ, Ab, Bb, 1, tid); CP_COMMIT();

    for (int kt = 0; kt < NK_IT; kt++) {
        CP_WAIT(1);                 // in-order completion: group kt is done
        __syncthreads();            // data visible; also guards ring reuse (WAR)
        if (kt + 2 < NK_IT)
            fill_stage(sb + ((kt + 2) % 3) * STG_SZ, Ab, Bb, kt + 2, tid);
        CP_COMMIT();                // keep one group per iter (empty ok)
        compute_stage(sb + (kt % 3) * STG_SZ, acc, lane, wm, wn);
    }
}

// ---------------- embed (+ fused emb-split into g_A2) ----------------
__global__ void __launch_bounds__(256) embed_kernel(const int* __restrict__ x,
                                                    const float* __restrict__ E,
                                                    const float* __restrict__ pe)
{
    int idx = blockIdx.x * 256 + threadIdx.x;
    int row = idx >> 8;
    int c   = (idx & 255) << 2;
    int tok = x[row];
    float4 e = *(const float4*)(E  + (size_t)tok * EMBED + c);
    float4 p = *(const float4*)(pe + (size_t)(row & 63) * EMBED + c);
    e.x += p.x; e.y += p.y; e.z += p.z; e.w += p.w;
    *(float4*)(g_emb + (size_t)row * EMBED + c) = e;

    __half2 l01, l23;
    __half2 h01 = split_hi2(e.x, e.y, l01);
    __half2 h23 = split_hi2(e.z, e.w, l23);
    size_t base = (size_t)row * K_EFF;
    *(__half2*)(g_A2 + base + c)            = h01;
    *(__half2*)(g_A2 + base + c + 2)        = h23;
    *(__half2*)(g_A2 + base + 1024 + c)     = l01;
    *(__half2*)(g_A2 + base + 1024 + c + 2) = l23;
}

// ---------------- weight prepasses (single fp16 section, K-major) ----------------
// Wq/Wk/Wv: [H][D][hd] -> g_Bqkv[z*1024 + n][k], n = h*64+e
__global__ void __launch_bounds__(256) conv_w_qkv(const float* __restrict__ Wq,
                                                  const float* __restrict__ Wk,
                                                  const float* __restrict__ Wv)
{
    __shared__ float t[32][33];
    const float* W = (blockIdx.z == 0) ? Wq : (blockIdx.z == 1) ? Wk : Wv;
    int n0 = blockIdx.x * 32;
    int k0 = blockIdx.y * 32;
    int tx = threadIdx.x, ty = threadIdx.y;   // 32 x 8
    int h  = n0 >> 6, e0 = n0 & 63;
    #pragma unroll
    for (int i = 0; i < 4; i++) {
        int kk = ty + i * 8;
        t[kk][tx] = W[(size_t)h * (EMBED * HDIM) + (size_t)(k0 + kk) * HDIM + e0 + tx];
    }
    __syncthreads();
    #pragma unroll
    for (int i = 0; i < 4; i++) {
        int nn = ty + i * 8;
        int k  = k0 + tx;
        g_Bqkv[(size_t)(blockIdx.z * 1024 + n0 + nn) * KB_DIM + k] =
            __float2half_rn(t[tx][nn]);
    }
}

// Wo: [1024 k][1024 n] row-major -> g_Bwo[n][k]
__global__ void __launch_bounds__(256) conv_w_o(const float* __restrict__ Wo)
{
    __shared__ float t[32][33];
    int n0 = blockIdx.x * 32;
    int k0 = blockIdx.y * 32;
    int tx = threadIdx.x, ty = threadIdx.y;
    #pragma unroll
    for (int i = 0; i < 4; i++) {
        int kk = ty + i * 8;
        t[kk][tx] = Wo[(size_t)(k0 + kk) * EMBED + n0 + tx];
    }
    __syncthreads();
    #pragma unroll
    for (int i = 0; i < 4; i++) {
        int nn = ty + i * 8;
        int k  = k0 + tx;
        g_Bwo[(size_t)(n0 + nn) * KB_DIM + k] = __float2half_rn(t[tx][nn]);
    }
}

// Wu: [1024 k][VOCAB n] (odd stride -> scalar loads) -> g_B2[n][k]
__global__ void __launch_bounds__(256) conv_wu_kernel(const float* __restrict__ Wu)
{
    __shared__ float t[32][33];
    int n0 = blockIdx.x * 32;
    int k0 = blockIdx.y * 32;
    int tx = threadIdx.x, ty = threadIdx.y;
    #pragma unroll
    for (int i = 0; i < 4; i++) {
        int k = k0 + ty + i * 8;
        int n = n0 + tx;
        t[ty + i * 8][tx] = (n < VOCAB) ? Wu[(size_t)k * VOCAB + n] : 0.f;
    }
    __syncthreads();
    #pragma unroll
    for (int i = 0; i < 4; i++) {
        int n = n0 + ty + i * 8;
        int k = k0 + tx;
        g_B2[(size_t)n * KB_DIM + k] = __float2half_rn(t[tx][ty + i * 8]);
    }
}

// ---------------- cat -> split (g_A2 reuse) ----------------
__global__ void __launch_bounds__(256) conv_cat_kernel()
{
    int idx = blockIdx.x * 256 + threadIdx.x;    // float4 index
    int row = idx >> 8;
    int c   = (idx & 255) << 2;
    float4 v = *(const float4*)(g_cat + (size_t)row * EMBED + c);
    __half2 l01, l23;
    __half2 h01 = split_hi2(v.x, v.y, l01);
    __half2 h23 = split_hi2(v.z, v.w, l23);
    size_t base = (size_t)row * K_EFF;
    *(__half2*)(g_A2 + base + c)            = h01;
    *(__half2*)(g_A2 + base + c + 2)        = h23;
    *(__half2*)(g_A2 + base + 1024 + c)     = l01;
    *(__half2*)(g_A2 + base + 1024 + c + 2) = l23;
}

// ---------------- attention (fp32, unchanged) ----------------
__global__ void __launch_bounds__(256) attn_kernel()
{
    __shared__ float sQ [64][68];
    __shared__ float sKV[64][68];
    int bh  = blockIdx.x;
    int tid = threadIdx.x;
    const float* qb = g_q + (size_t)bh * (SEQ * HDIM);
    const float* kb = g_k + (size_t)bh * (SEQ * HDIM);
    const float* vb = g_v + (size_t)bh * (SEQ * HDIM);
    #pragma unroll
    for (int i = 0; i < 4; i++) {
        int idx = tid + i * 256;
        int r = idx >> 4, c = (idx & 15) << 2;
        *(float4*)(&sQ [r][c]) = *(const float4*)(qb + r * 64 + c);
        *(float4*)(&sKV[r][c]) = *(const float4*)(kb + r * 64 + c);
    }
    __syncthreads();

    int s = tid >> 2, q = tid & 3;
    float4 qv[16];
    #pragma unroll
    for (int k4 = 0; k4 < 16; k4++) qv[k4] = *(const float4*)(&sQ[s][k4 * 4]);

    float sc[16];
    #pragma unroll
    for (int j = 0; j < 16; j++) {
        int t = q + 4 * j;
        float d = 0.f;
        #pragma unroll
        for (int k4 = 0; k4 < 16; k4++) {
            float4 kv = *(const float4*)(&sKV[t][k4 * 4]);
            d += qv[k4].x * kv.x + qv[k4].y * kv.y + qv[k4].z * kv.z + qv[k4].w * kv.w;
        }
        sc[j] = (t <= s) ? d * 0.125f : -1e30f;
    }
    float mx = sc[0];
    #pragma unroll
    for (int j = 1; j < 16; j++) mx = fmaxf(mx, sc[j]);
    mx = fmaxf(mx, __shfl_xor_sync(0xFFFFFFFFu, mx, 1));
    mx = fmaxf(mx, __shfl_xor_sync(0xFFFFFFFFu, mx, 2));
    float sum = 0.f;
    #pragma unroll
    for (int j = 0; j < 16; j++) { sc[j] = __expf(sc[j] - mx); sum += sc[j]; }
    sum += __shfl_xor_sync(0xFFFFFFFFu, sum, 1);
    sum += __shfl_xor_sync(0xFFFFFFFFu, sum, 2);
    float inv = 1.f / sum;
    #pragma unroll
    for (int j = 0; j < 16; j++) sc[j] *= inv;

    __syncthreads();
    #pragma unroll
    for (int i = 0; i < 4; i++) {
        int idx = tid + i * 256;
        int r = idx >> 4, c = (idx & 15) << 2;
        *(float4*)(&sKV[r][c]) = *(const float4*)(vb + r * 64 + c);
    }
    __syncthreads();

    float po[64];
    #pragma unroll
    for (int e = 0; e < 64; e++) po[e] = 0.f;
    #pragma unroll
    for (int j = 0; j < 16; j++) {
        int t = q + 4 * j;
        float w = sc[j];
        #pragma unroll
        for (int e4 = 0; e4 < 16; e4++) {
            float4 v = *(const float4*)(&sKV[t][e4 * 4]);
            po[e4 * 4 + 0] += w * v.x;
            po[e4 * 4 + 1] += w * v.y;
            po[e4 * 4 + 2] += w * v.z;
            po[e4 * 4 + 3] += w * v.w;
        }
    }
    #pragma unroll
    for (int e = 0; e < 64; e++) {
        po[e] += __shfl_xor_sync(0xFFFFFFFFu, po[e], 1);
        po[e] += __shfl_xor_sync(0xFFFFFFFFu, po[e], 2);
    }
    int b = bh >> 4, h = bh & 15;
    float* dst = g_cat + (size_t)b * (SEQ * EMBED) + (size_t)s * EMBED + h * HDIM + q * 16;
    #pragma unroll
    for (int i = 0; i < 4; i++) {
        int e0 = q * 16 + i * 4;
        *(float4*)(dst + i * 4) = make_float4(po[e0], po[e0 + 1], po[e0 + 2], po[e0 + 3]);
    }
}

// ---------------- QKV on HMMA: [emb-split] @ fp16([Wq|Wk|Wv]) ----------------
__global__ void __launch_bounds__(256, 2) qkv_mma(const float* __restrict__ bq,
                                                  const float* __restrict__ bk,
                                                  const float* __restrict__ bv)
{
    extern __shared__ char sm[];
    const int tid = threadIdx.x, lane = tid & 31, wid = tid >> 5;
    const int wm = (wid & 1) * 64, wn = (wid >> 1) * 32;
    const int m0 = blockIdx.x * 128;
    const int n0 = blockIdx.y * 128;     // global n in [0, 3072)

    float acc[4][4][4];
    hmma_loop(g_A2 + (size_t)m0 * K_EFF, g_Bqkv + (size_t)n0 * KB_DIM,
              sm, acc, tid, lane, wm, wn);

    const int which = n0 >> 10;          // uniform per CTA
    float* outp = (which == 0) ? g_q : (which == 1) ? g_k : g_v;
    const float* bias = (which == 0) ? bq : (which == 1) ? bk : bv;

    const int er = lane >> 2;
    const int ec = (lane & 3) * 2;
    #pragma unroll
    for (int mi = 0; mi < 4; mi++) {
        #pragma unroll
        for (int nj = 0; nj < 4; nj++) {
            int col = n0 + wn + nj * 8 + ec;      // global
            int n   = col & 1023;                  // within weight
            int h = n >> 6, e = n & 63;
            float b0v = bias[n], b1v = bias[n + 1];
            int row0 = m0 + wm + mi * 16 + er;
            #pragma unroll
            for (int half = 0; half < 2; half++) {
                int row = row0 + half * 8;
                int b = row >> 6, s = row & 63;
                float* dst = outp + (size_t)(((b * NHEAD + h) * SEQ + s) * HDIM + e);
                *(float2*)dst = make_float2(acc[mi][nj][half * 2] + b0v,
                                            acc[mi][nj][half * 2 + 1] + b1v);
            }
        }
    }
}

// ---------------- Wo on HMMA: y = cat-split @ fp16(Wo) + bo + emb; emit y-split ----------------
__global__ void __launch_bounds__(256, 2) wo_mma(const float* __restrict__ bo)
{
    extern __shared__ char sm[];
    const int tid = threadIdx.x, lane = tid & 31, wid = tid >> 5;
    const int wm = (wid & 1) * 64, wn = (wid >> 1) * 32;
    const int m0 = blockIdx.x * 128;
    const int n0 = blockIdx.y * 128;

    float acc[4][4][4];
    hmma_loop(g_A2 + (size_t)m0 * K_EFF, g_Bwo + (size_t)n0 * KB_DIM,
              sm, acc, tid, lane, wm, wn);

    const int er = lane >> 2;
    const int ec = (lane & 3) * 2;
    #pragma unroll
    for (int mi = 0; mi < 4; mi++) {
        #pragma unroll
        for (int nj = 0; nj < 4; nj++) {
            int col = n0 + wn + nj * 8 + ec;
            float b0v = bo[col], b1v = bo[col + 1];
            int row0 = m0 + wm + mi * 16 + er;
            #pragma unroll
            for (int half = 0; half < 2; half++) {
                int row = row0 + half * 8;
                float2 em = *(const float2*)(g_emb + (size_t)row * EMBED + col);
                float y0 = acc[mi][nj][half * 2]     + b0v + em.x;
                float y1 = acc[mi][nj][half * 2 + 1] + b1v + em.y;
                __half2 lo;
                __half2 hi = split_hi2(y0, y1, lo);
                size_t base = (size_t)row * K_EFF + col;
                *(__half2*)(g_A3 + base)        = hi;
                *(__half2*)(g_A3 + base + 1024) = lo;
            }
        }
    }
}

// ---------------- logits on HMMA: out = y-split @ fp16(Wu) + bu ----------------
// out rows have odd stride (VOCAB) -> scalar stores only.
__global__ void __launch_bounds__(256, 2) wu_mma(const float* __restrict__ bu,
                                                 float* __restrict__ out)
{
    extern __shared__ char sm[];
    const int tid = threadIdx.x, lane = tid & 31, wid = tid >> 5;
    const int wm = (wid & 1) * 64, wn = (wid >> 1) * 32;
    const int m0 = blockIdx.x * 128;
    const int n0 = blockIdx.y * 128;

    float acc[4][4][4];
    hmma_loop(g_A3 + (size_t)m0 * K_EFF, g_B2 + (size_t)n0 * KB_DIM,
              sm, acc, tid, lane, wm, wn);

    const int er = lane >> 2;
    const int ec = (lane & 3) * 2;
    #pragma unroll
    for (int mi = 0; mi < 4; mi++) {
        #pragma unroll
        for (int nj = 0; nj < 4; nj++) {
            int col = n0 + wn + nj * 8 + ec;
            float b0v = (col < VOCAB)     ? __ldg(bu + col)     : 0.f;
            float b1v = (col + 1 < VOCAB) ? __ldg(bu + col + 1) : 0.f;
            int row = m0 + wm + mi * 16 + er;
            float* p0 = out + (size_t)row * VOCAB + col;
            float* p1 = out + (size_t)(row + 8) * VOCAB + col;
            if (col < VOCAB) {
                p0[0] = acc[mi][nj][0] + b0v;
                p1[0] = acc[mi][nj][2] + b0v;
            }
            if (col + 1 < VOCAB) {
                p0[1] = acc[mi][nj][1] + b1v;
                p1[1] = acc[mi][nj][3] + b1v;
            }
        }
    }
}

// ---------------- launch ----------------
#define MMA_SMEM (3 * STG_SZ)   /* 98304 */

extern "C" void kernel_launch(void* const* d_in, const int* in_sizes, int n_in,
                              void* d_out, int out_size)
{
    const int*   x  = (const int*)  d_in[0];
    const float* E  = (const float*)d_in[1];
    const float* pe = (const float*)d_in[2];
    const float* Wq = (const float*)d_in[3];
    const float* bq = (const float*)d_in[4];
    const float* Wk = (const float*)d_in[5];
    const float* bk = (const float*)d_in[6];
    const float* Wv = (const float*)d_in[7];
    const float* bv = (const float*)d_in[8];
    const float* Wo = (const float*)d_in[9];
    const float* bo = (const float*)d_in[10];
    const float* Wu = (const float*)d_in[11];
    const float* bu = (const float*)d_in[12];
    float* out = (float*)d_out;

    cudaFuncSetAttribute(qkv_mma, cudaFuncAttributeMaxDynamicSharedMemorySize, MMA_SMEM);
    cudaFuncSetAttribute(wo_mma,  cudaFuncAttributeMaxDynamicSharedMemorySize, MMA_SMEM);
    cudaFuncSetAttribute(wu_mma,  cudaFuncAttributeMaxDynamicSharedMemorySize, MMA_SMEM);

    embed_kernel<<<4096, 256>>>(x, E, pe);                              // emb + emb-split
    conv_w_qkv<<<dim3(32, 32, 3), dim3(32, 8)>>>(Wq, Wk, Wv);           // weight fp16
    conv_w_o  <<<dim3(32, 32),    dim3(32, 8)>>>(Wo);
    conv_wu_kernel<<<dim3(N_PAD / 32, EMBED / 32), dim3(32, 8)>>>(Wu);

    qkv_mma<<<dim3(32, 24), 256, MMA_SMEM>>>(bq, bk, bv);               // q,k,v

    attn_kernel<<<BATCH * NHEAD, 256>>>();                              // -> cat

    conv_cat_kernel<<<4096, 256>>>();                                   // cat-split -> g_A2
    wo_mma<<<dim3(32, 8), 256, MMA_SMEM>>>(bo);                         // y-split -> g_A3

    wu_mma<<<dim3(32, N_PAD / 128), 256, MMA_SMEM>>>(bu, out);          // logits
}

// round 11
// speedup vs baseline: 6.5875x; 1.5384x over previous
#include <cuda_runtime.h>
#include <cuda_fp16.h>
#include <cstdint>

#define BATCH 64
#define SEQ   64
#define EMBED 1024
#define NHEAD 16
#define HDIM  64
#define VOCAB 50257
#define M_TOT (BATCH*SEQ)   /* 4096 */

#define N_PAD  50304        /* 393*128 */
#define K_EFF  2048         /* A sections for qkv/wo: [hi | lo] fp16 */
#define KB_DIM 1024         /* B single fp16 section; also wu A (y-hi) stride */
#define NK_QKV 32           /* K_EFF / 64 */
#define NK_WU  16           /* KB_DIM / 64 */

// ---------------- scratch (no allocation allowed) ----------------
__device__ float g_emb[M_TOT*EMBED];
__device__ float g_q  [M_TOT*EMBED];
__device__ float g_k  [M_TOT*EMBED];
__device__ float g_v  [M_TOT*EMBED];
__device__ float g_cat[M_TOT*EMBED];
// fp16 operands (K-major)
__device__ __align__(16) __half g_A2  [(size_t)M_TOT * K_EFF];    // [hi|lo] emb-split, then cat-split
__device__ __align__(16) __half g_A3  [(size_t)M_TOT * KB_DIM];   // y-hi only
__device__ __align__(16) __half g_Bqkv[(size_t)3072  * KB_DIM];   // [Wq|Wk|Wv]
__device__ __align__(16) __half g_Bwo [(size_t)EMBED * KB_DIM];   // Wo
__device__ __align__(16) __half g_B2  [(size_t)N_PAD * KB_DIM];   // Wu

// ---------------- helpers ----------------
__device__ __forceinline__ uint32_t smem_u32(const void* p) {
    uint32_t a;
    asm("{ .reg .u64 t; cvta.to.shared.u64 t, %1; cvt.u32.u64 %0, t; }" : "=r"(a) : "l"(p));
    return a;
}
__device__ __forceinline__ void cp16(uint32_t dst, const void* src) {
    asm volatile("cp.async.cg.shared.global [%0], [%1], 16;" :: "r"(dst), "l"(src) : "memory");
}
#define CP_COMMIT() asm volatile("cp.async.commit_group;" ::: "memory")
#define CP_WAIT(N)  asm volatile("cp.async.wait_group %0;" :: "n"(N) : "memory")

__device__ __forceinline__ void ldm_x4(uint32_t (&r)[4], uint32_t addr) {
    asm volatile("ldmatrix.sync.aligned.m8n8.x4.shared.b16 {%0,%1,%2,%3}, [%4];"
        : "=r"(r[0]), "=r"(r[1]), "=r"(r[2]), "=r"(r[3]) : "r"(addr));
}
__device__ __forceinline__ void mma_f16(float (&d)[4], const uint32_t (&a)[4],
                                        uint32_t b0, uint32_t b1) {
    asm volatile("mma.sync.aligned.m16n8k16.row.col.f32.f16.f16.f32 "
        "{%0,%1,%2,%3}, {%4,%5,%6,%7}, {%8,%9}, {%0,%1,%2,%3};"
        : "+f"(d[0]), "+f"(d[1]), "+f"(d[2]), "+f"(d[3])
        : "r"(a[0]), "r"(a[1]), "r"(a[2]), "r"(a[3]), "r"(b0), "r"(b1));
}
__device__ __forceinline__ __half2 split_hi2(float a, float b, __half2& lo) {
    __half ha = __float2half_rn(a);
    __half hb = __float2half_rn(b);
    lo = __half2(__float2half_rn(a - __half2float(ha)),
                 __float2half_rn(b - __half2float(hb)));
    return __half2(ha, hb);
}

// ================= shared HMMA mainloop =================
// CTA tile 128(m) x 128(n). A stride/section count parameterized; B: KB_DIM repeated (kt & 15).
// k-chunk 64 per stage, 3-stage cp.async ring.
// Stage layout (32KB): A [2 sub][128 rows][32 fp16 (64B, XOR swizzled)], B same at +16KB.
#define STG_SZ 32768

__device__ __forceinline__ void fill_stage(uint32_t sbase, const __half* Ab, int strideA,
                                           const __half* Bb, int kt, int tid)
{
    const int ka = kt * 64;
    const int kb = (kt & 15) * 64;
    #pragma unroll
    for (int i = 0; i < 4; i++) {
        int c = tid + i * 256;                 // 0..1023
        int row = c >> 3, ck = c & 7;
        uint32_t off = (ck >> 2) * 8192 + row * 64 + (((ck & 3) ^ ((row >> 1) & 3)) << 4);
        cp16(sbase + off, Ab + (size_t)row * strideA + ka + ck * 8);
    }
    #pragma unroll
    for (int i = 0; i < 4; i++) {
        int c = tid + i * 256;
        int row = c >> 3, ck = c & 7;
        uint32_t off = 16384 + (ck >> 2) * 8192 + row * 64 + (((ck & 3) ^ ((row >> 1) & 3)) << 4);
        cp16(sbase + off, Bb + (size_t)row * KB_DIM + kb + ck * 8);
    }
}

__device__ __forceinline__ void compute_stage(uint32_t sbase, float (&acc)[4][4][4],
                                              int lane, int wm, int wn)
{
    const int a_r8 = (lane & 7) + ((lane >> 3) & 1) * 8;
    const int a_kh = (lane >> 4) * 8;
    const int b_r8 = (lane & 7) + (lane >> 4) * 8;
    const int b_kh = ((lane >> 3) & 1) * 8;
    #pragma unroll
    for (int sub = 0; sub < 2; sub++) {
        const uint32_t A0 = sbase + sub * 8192;
        const uint32_t B0 = sbase + 16384 + sub * 8192;
        #pragma unroll
        for (int ks = 0; ks < 32; ks += 16) {
            uint32_t af[4][4], bf[4][2];
            #pragma unroll
            for (int mi = 0; mi < 4; mi++) {
                int row = wm + mi * 16 + a_r8;
                int kk  = ks + a_kh;
                ldm_x4(af[mi], A0 + row * 64 + (((kk >> 3) ^ ((row >> 1) & 3)) << 4));
            }
            #pragma unroll
            for (int nj = 0; nj < 2; nj++) {
                int row = wn + nj * 16 + b_r8;
                int kk  = ks + b_kh;
                uint32_t t[4];
                ldm_x4(t, B0 + row * 64 + (((kk >> 3) ^ ((row >> 1) & 3)) << 4));
                bf[nj * 2][0]     = t[0]; bf[nj * 2][1]     = t[1];
                bf[nj * 2 + 1][0] = t[2]; bf[nj * 2 + 1][1] = t[3];
            }
            #pragma unroll
            for (int mi = 0; mi < 4; mi++)
                #pragma unroll
                for (int nj = 0; nj < 4; nj++)
                    mma_f16(acc[mi][nj], af[mi], bf[nj][0], bf[nj][1]);
        }
    }
}

__device__ __forceinline__ void hmma_loop(const __half* Ab, int strideA,
                                          const __half* Bb, int nk,
                                          char* sm, float (&acc)[4][4][4],
                                          int tid, int lane, int wm, int wn)
{
    #pragma unroll
    for (int i = 0; i < 4; i++)
        #pragma unroll
        for (int j = 0; j < 4; j++)
            #pragma unroll
            for (int r = 0; r < 4; r++) acc[i][j][r] = 0.f;

    const uint32_t sb = smem_u32(sm);
    fill_stage(sb,          Ab, strideA, Bb, 0, tid); CP_COMMIT();
    fill_stage(sb + STG_SZ, Ab, strideA, Bb, 1, tid); CP_COMMIT();

    for (int kt = 0; kt < nk; kt++) {
        CP_WAIT(1);                 // in-order completion: group kt is done
        __syncthreads();            // data visible; also guards ring reuse (WAR)
        if (kt + 2 < nk)
            fill_stage(sb + ((kt + 2) % 3) * STG_SZ, Ab, strideA, Bb, kt + 2, tid);
        CP_COMMIT();                // keep one group per iter (empty ok)
        compute_stage(sb + (kt % 3) * STG_SZ, acc, lane, wm, wn);
    }
}

// ---------------- embed (+ fused emb-split into g_A2) ----------------
__global__ void __launch_bounds__(256) embed_kernel(const int* __restrict__ x,
                                                    const float* __restrict__ E,
                                                    const float* __restrict__ pe)
{
    int idx = blockIdx.x * 256 + threadIdx.x;
    int row = idx >> 8;
    int c   = (idx & 255) << 2;
    int tok = x[row];
    float4 e = *(const float4*)(E  + (size_t)tok * EMBED + c);
    float4 p = *(const float4*)(pe + (size_t)(row & 63) * EMBED + c);
    e.x += p.x; e.y += p.y; e.z += p.z; e.w += p.w;
    *(float4*)(g_emb + (size_t)row * EMBED + c) = e;

    __half2 l01, l23;
    __half2 h01 = split_hi2(e.x, e.y, l01);
    __half2 h23 = split_hi2(e.z, e.w, l23);
    size_t base = (size_t)row * K_EFF;
    *(__half2*)(g_A2 + base + c)            = h01;
    *(__half2*)(g_A2 + base + c + 2)        = h23;
    *(__half2*)(g_A2 + base + 1024 + c)     = l01;
    *(__half2*)(g_A2 + base + 1024 + c + 2) = l23;
}

// ---------------- weight prepasses (single fp16 section, K-major) ----------------
__global__ void __launch_bounds__(256) conv_w_qkv(const float* __restrict__ Wq,
                                                  const float* __restrict__ Wk,
                                                  const float* __restrict__ Wv)
{
    __shared__ float t[32][33];
    const float* W = (blockIdx.z == 0) ? Wq : (blockIdx.z == 1) ? Wk : Wv;
    int n0 = blockIdx.x * 32;
    int k0 = blockIdx.y * 32;
    int tx = threadIdx.x, ty = threadIdx.y;   // 32 x 8
    int h  = n0 >> 6, e0 = n0 & 63;
    #pragma unroll
    for (int i = 0; i < 4; i++) {
        int kk = ty + i * 8;
        t[kk][tx] = W[(size_t)h * (EMBED * HDIM) + (size_t)(k0 + kk) * HDIM + e0 + tx];
    }
    __syncthreads();
    #pragma unroll
    for (int i = 0; i < 4; i++) {
        int nn = ty + i * 8;
        int k  = k0 + tx;
        g_Bqkv[(size_t)(blockIdx.z * 1024 + n0 + nn) * KB_DIM + k] =
            __float2half_rn(t[tx][nn]);
    }
}

__global__ void __launch_bounds__(256) conv_w_o(const float* __restrict__ Wo)
{
    __shared__ float t[32][33];
    int n0 = blockIdx.x * 32;
    int k0 = blockIdx.y * 32;
    int tx = threadIdx.x, ty = threadIdx.y;
    #pragma unroll
    for (int i = 0; i < 4; i++) {
        int kk = ty + i * 8;
        t[kk][tx] = Wo[(size_t)(k0 + kk) * EMBED + n0 + tx];
    }
    __syncthreads();
    #pragma unroll
    for (int i = 0; i < 4; i++) {
        int nn = ty + i * 8;
        int k  = k0 + tx;
        g_Bwo[(size_t)(n0 + nn) * KB_DIM + k] = __float2half_rn(t[tx][nn]);
    }
}

// Wu: [1024 k][VOCAB n] (odd stride -> scalar loads) -> g_B2[n][k]
__global__ void __launch_bounds__(256) conv_wu_kernel(const float* __restrict__ Wu)
{
    __shared__ float t[32][33];
    int n0 = blockIdx.x * 32;
    int k0 = blockIdx.y * 32;
    int tx = threadIdx.x, ty = threadIdx.y;
    #pragma unroll
    for (int i = 0; i < 4; i++) {
        int k = k0 + ty + i * 8;
        int n = n0 + tx;
        t[ty + i * 8][tx] = (n < VOCAB) ? Wu[(size_t)k * VOCAB + n] : 0.f;
    }
    __syncthreads();
    #pragma unroll
    for (int i = 0; i < 4; i++) {
        int n = n0 + ty + i * 8;
        int k = k0 + tx;
        g_B2[(size_t)n * KB_DIM + k] = __float2half_rn(t[tx][ty + i * 8]);
    }
}

// ---------------- cat -> split (g_A2 reuse) ----------------
__global__ void __launch_bounds__(256) conv_cat_kernel()
{
    int idx = blockIdx.x * 256 + threadIdx.x;    // float4 index
    int row = idx >> 8;
    int c   = (idx & 255) << 2;
    float4 v = *(const float4*)(g_cat + (size_t)row * EMBED + c);
    __half2 l01, l23;
    __half2 h01 = split_hi2(v.x, v.y, l01);
    __half2 h23 = split_hi2(v.z, v.w, l23);
    size_t base = (size_t)row * K_EFF;
    *(__half2*)(g_A2 + base + c)            = h01;
    *(__half2*)(g_A2 + base + c + 2)        = h23;
    *(__half2*)(g_A2 + base + 1024 + c)     = l01;
    *(__half2*)(g_A2 + base + 1024 + c + 2) = l23;
}

// ---------------- attention (fp32, unchanged) ----------------
__global__ void __launch_bounds__(256) attn_kernel()
{
    __shared__ float sQ [64][68];
    __shared__ float sKV[64][68];
    int bh  = blockIdx.x;
    int tid = threadIdx.x;
    const float* qb = g_q + (size_t)bh * (SEQ * HDIM);
    const float* kb = g_k + (size_t)bh * (SEQ * HDIM);
    const float* vb = g_v + (size_t)bh * (SEQ * HDIM);
    #pragma unroll
    for (int i = 0; i < 4; i++) {
        int idx = tid + i * 256;
        int r = idx >> 4, c = (idx & 15) << 2;
        *(float4*)(&sQ [r][c]) = *(const float4*)(qb + r * 64 + c);
        *(float4*)(&sKV[r][c]) = *(const float4*)(kb + r * 64 + c);
    }
    __syncthreads();

    int s = tid >> 2, q = tid & 3;
    float4 qv[16];
    #pragma unroll
    for (int k4 = 0; k4 < 16; k4++) qv[k4] = *(const float4*)(&sQ[s][k4 * 4]);

    float sc[16];
    #pragma unroll
    for (int j = 0; j < 16; j++) {
        int t = q + 4 * j;
        float d = 0.f;
        #pragma unroll
        for (int k4 = 0; k4 < 16; k4++) {
            float4 kv = *(const float4*)(&sKV[t][k4 * 4]);
            d += qv[k4].x * kv.x + qv[k4].y * kv.y + qv[k4].z * kv.z + qv[k4].w * kv.w;
        }
        sc[j] = (t <= s) ? d * 0.125f : -1e30f;
    }
    float mx = sc[0];
    #pragma unroll
    for (int j = 1; j < 16; j++) mx = fmaxf(mx, sc[j]);
    mx = fmaxf(mx, __shfl_xor_sync(0xFFFFFFFFu, mx, 1));
    mx = fmaxf(mx, __shfl_xor_sync(0xFFFFFFFFu, mx, 2));
    float sum = 0.f;
    #pragma unroll
    for (int j = 0; j < 16; j++) { sc[j] = __expf(sc[j] - mx); sum += sc[j]; }
    sum += __shfl_xor_sync(0xFFFFFFFFu, sum, 1);
    sum += __shfl_xor_sync(0xFFFFFFFFu, sum, 2);
    float inv = 1.f / sum;
    #pragma unroll
    for (int j = 0; j < 16; j++) sc[j] *= inv;

    __syncthreads();
    #pragma unroll
    for (int i = 0; i < 4; i++) {
        int idx = tid + i * 256;
        int r = idx >> 4, c = (idx & 15) << 2;
        *(float4*)(&sKV[r][c]) = *(const float4*)(vb + r * 64 + c);
    }
    __syncthreads();

    float po[64];
    #pragma unroll
    for (int e = 0; e < 64; e++) po[e] = 0.f;
    #pragma unroll
    for (int j = 0; j < 16; j++) {
        int t = q + 4 * j;
        float w = sc[j];
        #pragma unroll
        for (int e4 = 0; e4 < 16; e4++) {
            float4 v = *(const float4*)(&sKV[t][e4 * 4]);
            po[e4 * 4 + 0] += w * v.x;
            po[e4 * 4 + 1] += w * v.y;
            po[e4 * 4 + 2] += w * v.z;
            po[e4 * 4 + 3] += w * v.w;
        }
    }
    #pragma unroll
    for (int e = 0; e < 64; e++) {
        po[e] += __shfl_xor_sync(0xFFFFFFFFu, po[e], 1);
        po[e] += __shfl_xor_sync(0xFFFFFFFFu, po[e], 2);
    }
    int b = bh >> 4, h = bh & 15;
    float* dst = g_cat + (size_t)b * (SEQ * EMBED) + (size_t)s * EMBED + h * HDIM + q * 16;
    #pragma unroll
    for (int i = 0; i < 4; i++) {
        int e0 = q * 16 + i * 4;
        *(float4*)(dst + i * 4) = make_float4(po[e0], po[e0 + 1], po[e0 + 2], po[e0 + 3]);
    }
}

// ---------------- QKV on HMMA: [emb-split] @ fp16([Wq|Wk|Wv]) ----------------
__global__ void __launch_bounds__(256, 2) qkv_mma(const float* __restrict__ bq,
                                                  const float* __restrict__ bk,
                                                  const float* __restrict__ bv)
{
    extern __shared__ char sm[];
    const int tid = threadIdx.x, lane = tid & 31, wid = tid >> 5;
    const int wm = (wid & 1) * 64, wn = (wid >> 1) * 32;
    const int m0 = blockIdx.x * 128;
    const int n0 = blockIdx.y * 128;     // global n in [0, 3072)

    float acc[4][4][4];
    hmma_loop(g_A2 + (size_t)m0 * K_EFF, K_EFF,
              g_Bqkv + (size_t)n0 * KB_DIM, NK_QKV,
              sm, acc, tid, lane, wm, wn);

    const int which = n0 >> 10;          // uniform per CTA
    float* outp = (which == 0) ? g_q : (which == 1) ? g_k : g_v;
    const float* bias = (which == 0) ? bq : (which == 1) ? bk : bv;

    const int er = lane >> 2;
    const int ec = (lane & 3) * 2;
    #pragma unroll
    for (int mi = 0; mi < 4; mi++) {
        #pragma unroll
        for (int nj = 0; nj < 4; nj++) {
            int col = n0 + wn + nj * 8 + ec;      // global
            int n   = col & 1023;                  // within weight
            int h = n >> 6, e = n & 63;
            float b0v = bias[n], b1v = bias[n + 1];
            int row0 = m0 + wm + mi * 16 + er;
            #pragma unroll
            for (int half = 0; half < 2; half++) {
                int row = row0 + half * 8;
                int b = row >> 6, s = row & 63;
                float* dst = outp + (size_t)(((b * NHEAD + h) * SEQ + s) * HDIM + e);
                *(float2*)dst = make_float2(acc[mi][nj][half * 2] + b0v,
                                            acc[mi][nj][half * 2 + 1] + b1v);
            }
        }
    }
}

// ---------------- Wo on HMMA: y = cat-split @ fp16(Wo) + bo + emb; emit fp16(y) ----------------
__global__ void __launch_bounds__(256, 2) wo_mma(const float* __restrict__ bo)
{
    extern __shared__ char sm[];
    const int tid = threadIdx.x, lane = tid & 31, wid = tid >> 5;
    const int wm = (wid & 1) * 64, wn = (wid >> 1) * 32;
    const int m0 = blockIdx.x * 128;
    const int n0 = blockIdx.y * 128;

    float acc[4][4][4];
    hmma_loop(g_A2 + (size_t)m0 * K_EFF, K_EFF,
              g_Bwo + (size_t)n0 * KB_DIM, NK_QKV,
              sm, acc, tid, lane, wm, wn);

    const int er = lane >> 2;
    const int ec = (lane & 3) * 2;
    #pragma unroll
    for (int mi = 0; mi < 4; mi++) {
        #pragma unroll
        for (int nj = 0; nj < 4; nj++) {
            int col = n0 + wn + nj * 8 + ec;
            float b0v = bo[col], b1v = bo[col + 1];
            int row0 = m0 + wm + mi * 16 + er;
            #pragma unroll
            for (int half = 0; half < 2; half++) {
                int row = row0 + half * 8;
                float2 em = *(const float2*)(g_emb + (size_t)row * EMBED + col);
                float y0 = acc[mi][nj][half * 2]     + b0v + em.x;
                float y1 = acc[mi][nj][half * 2 + 1] + b1v + em.y;
                *(__half2*)(g_A3 + (size_t)row * KB_DIM + col) =
                    __half2(__float2half_rn(y0), __float2half_rn(y1));
            }
        }
    }
}

// ---------------- logits on HMMA: out = fp16(y) @ fp16(Wu) + bu ----------------
// out rows have odd stride (VOCAB) -> scalar stores only.
__global__ void __launch_bounds__(256, 2) wu_mma(const float* __restrict__ bu,
                                                 float* __restrict__ out)
{
    extern __shared__ char sm[];
    const int tid = threadIdx.x, lane = tid & 31, wid = tid >> 5;
    const int wm = (wid & 1) * 64, wn = (wid >> 1) * 32;
    const int m0 = blockIdx.x * 128;
    const int n0 = blockIdx.y * 128;

    float acc[4][4][4];
    hmma_loop(g_A3 + (size_t)m0 * KB_DIM, KB_DIM,
              g_B2 + (size_t)n0 * KB_DIM, NK_WU,
              sm, acc, tid, lane, wm, wn);

    const int er = lane >> 2;
    const int ec = (lane & 3) * 2;
    #pragma unroll
    for (int mi = 0; mi < 4; mi++) {
        #pragma unroll
        for (int nj = 0; nj < 4; nj++) {
            int col = n0 + wn + nj * 8 + ec;
            float b0v = (col < VOCAB)     ? __ldg(bu + col)     : 0.f;
            float b1v = (col + 1 < VOCAB) ? __ldg(bu + col + 1) : 0.f;
            int row = m0 + wm + mi * 16 + er;
            float* p0 = out + (size_t)row * VOCAB + col;
            float* p1 = out + (size_t)(row + 8) * VOCAB + col;
            if (col < VOCAB) {
                p0[0] = acc[mi][nj][0] + b0v;
                p1[0] = acc[mi][nj][2] + b0v;
            }
            if (col + 1 < VOCAB) {
                p0[1] = acc[mi][nj][1] + b1v;
                p1[1] = acc[mi][nj][3] + b1v;
            }
        }
    }
}

// ---------------- launch ----------------
#define MMA_SMEM (3 * STG_SZ)   /* 98304 */

extern "C" void kernel_launch(void* const* d_in, const int* in_sizes, int n_in,
                              void* d_out, int out_size)
{
    const int*   x  = (const int*)  d_in[0];
    const float* E  = (const float*)d_in[1];
    const float* pe = (const float*)d_in[2];
    const float* Wq = (const float*)d_in[3];
    const float* bq = (const float*)d_in[4];
    const float* Wk = (const float*)d_in[5];
    const float* bk = (const float*)d_in[6];
    const float* Wv = (const float*)d_in[7];
    const float* bv = (const float*)d_in[8];
    const float* Wo = (const float*)d_in[9];
    const float* bo = (const float*)d_in[10];
    const float* Wu = (const float*)d_in[11];
    const float* bu = (const float*)d_in[12];
    float* out = (float*)d_out;

    cudaFuncSetAttribute(qkv_mma, cudaFuncAttributeMaxDynamicSharedMemorySize, MMA_SMEM);
    cudaFuncSetAttribute(wo_mma,  cudaFuncAttributeMaxDynamicSharedMemorySize, MMA_SMEM);
    cudaFuncSetAttribute(wu_mma,  cudaFuncAttributeMaxDynamicSharedMemorySize, MMA_SMEM);

    embed_kernel<<<4096, 256>>>(x, E, pe);                              // emb + emb-split
    conv_w_qkv<<<dim3(32, 32, 3), dim3(32, 8)>>>(Wq, Wk, Wv);           // weight fp16
    conv_w_o  <<<dim3(32, 32),    dim3(32, 8)>>>(Wo);
    conv_wu_kernel<<<dim3(N_PAD / 32, EMBED / 32), dim3(32, 8)>>>(Wu);

    qkv_mma<<<dim3(32, 24), 256, MMA_SMEM>>>(bq, bk, bv);               // q,k,v

    attn_kernel<<<BATCH * NHEAD, 256>>>();                              // -> cat

    conv_cat_kernel<<<4096, 256>>>();                                   // cat-split -> g_A2
    wo_mma<<<dim3(32, 8), 256, MMA_SMEM>>>(bo);                         // y-hi -> g_A3

    wu_mma<<<dim3(32, N_PAD / 128), 256, MMA_SMEM>>>(bu, out);          // logits
}